// round 14
// baseline (speedup 1.0000x reference)
#include <cuda_runtime.h>
#include <math.h>

#define NN 50000
#define NE 800000
typedef unsigned long long ULL;

// ---------------- device scratch ----------------
__device__ float g_hin [NN * 128];
__device__ float g_pre1[NN * 64];
__device__ float g_pre2[NN * 64];
__device__ float g_pre3[NN * 64];
__device__ float g_pre4[NN * 64];
__device__ float g_wt0b[128 * 64];
__device__ float g_wt1a[64 * 64];
__device__ float g_wt1b[64 * 64];
__device__ float g_wt2a[64 * 64];
__device__ float g_wt2b[64 * 64];
__device__ float g_fc1t[320 * 64];
__device__ float g_U[1024 * 64];     // U[c][m] = x0_c @ fc1_w[:, :128]^T
__device__ float g_T[1024 * 128];    // T[c][m] = x0_c @ w0a^T
__device__ int   g_comb[NN];         // (deg*16+lab)*128
__device__ int   g_cnt[NN];
__device__ int   g_rowptr[NN + 1];
__device__ int   g_cursor[NN];
__device__ ULL   g_edge[NE];         // lo32 = src*64, hi32 = comb
__device__ unsigned int g_part[256];
__device__ float g_stats[4 * 128];

#define ASTRIDE 68    // 64-wide staging rows (tables_kernel)
#define NSTRIDE 132   // 128-wide staging rows (GEMM kernels), 16B-aligned

// ---------------- f32x2 helpers ----------------
__device__ __forceinline__ ULL pk2(float x, float y) {
    ULL r; asm("mov.b64 %0, {%1,%2};" : "=l"(r) : "f"(x), "f"(y)); return r;
}
__device__ __forceinline__ void upk(ULL v, float& x, float& y) {
    asm("mov.b64 {%0,%1}, %2;" : "=f"(x), "=f"(y) : "l"(v));
}
__device__ __forceinline__ void fma2(ULL& d, ULL a, ULL b) {
    asm("fma.rn.f32x2 %0, %1, %2, %0;" : "+l"(d) : "l"(a), "l"(b));
}

// 16-node GEMM micro-step: 2 weight cols (w0,w1) x 8 node-pairs
#define FMA_ROW(accA, accB, row, w0, w1) { \
    ulonglong2 _n01 = *(const ulonglong2*)(row); \
    ulonglong2 _n23 = *(const ulonglong2*)((row) + 4); \
    ulonglong2 _n45 = *(const ulonglong2*)((row) + 8); \
    ulonglong2 _n67 = *(const ulonglong2*)((row) + 12); \
    fma2(accA[0], w0, _n01.x); fma2(accA[1], w0, _n01.y); \
    fma2(accA[2], w0, _n23.x); fma2(accA[3], w0, _n23.y); \
    fma2(accA[4], w0, _n45.x); fma2(accA[5], w0, _n45.y); \
    fma2(accA[6], w0, _n67.x); fma2(accA[7], w0, _n67.y); \
    fma2(accB[0], w1, _n01.x); fma2(accB[1], w1, _n01.y); \
    fma2(accB[2], w1, _n23.x); fma2(accB[3], w1, _n23.y); \
    fma2(accB[4], w1, _n45.x); fma2(accB[5], w1, _n45.y); \
    fma2(accB[6], w1, _n67.x); fma2(accB[7], w1, _n67.y); }

// ---------------- CSR A1: histogram by dst + comb ----------
__global__ void hist_kernel(const int* __restrict__ dst,
                            const int* __restrict__ ndeg, const int* __restrict__ nlab,
                            int E, int N) {
    int i = blockIdx.x * blockDim.x + threadIdx.x;
    if (i < E) atomicAdd(&g_cnt[dst[i]], 1);
    if (i < N) g_comb[i] = (ndeg[i] * 16 + nlab[i]) << 7;
}

// ---------------- CSR A2: decoupled-lookback scan ----------
__global__ void scan_kernel(int N) {
    __shared__ int sm[256];
    __shared__ int s_base;
    const int b = blockIdx.x;
    const int t = threadIdx.x;
    int idx = b * 256 + t;
    int v = (idx < N) ? g_cnt[idx] : 0;
    sm[t] = v;
    __syncthreads();
    for (int o = 1; o < 256; o <<= 1) {
        int u = (t >= o) ? sm[t - o] : 0;
        __syncthreads(); sm[t] += u; __syncthreads();
    }
    if (t == 255) {
        int total = sm[255];
        if (b == 0) {
            atomicExch(&g_part[0], 0x80000000u | (unsigned)total);
            s_base = 0;
        } else {
            atomicExch(&g_part[b], 0x40000000u | (unsigned)total);
            int excl = 0;
            for (int p = b - 1;;) {
                unsigned pv;
                do { pv = atomicAdd(&g_part[p], 0u); } while (pv < 0x40000000u);
                excl += (int)(pv & 0x3FFFFFFFu);
                if (pv >= 0x80000000u) break;
                p--;
            }
            atomicExch(&g_part[b], 0x80000000u | (unsigned)(excl + total));
            s_base = excl;
        }
    }
    __syncthreads();
    int excl_local = sm[t] - v + s_base;
    if (idx < N) {
        g_rowptr[idx] = excl_local;
        g_cursor[idx] = excl_local;
        if (idx == N - 1) g_rowptr[N] = excl_local + v;
    }
}

// ---------------- CSR A3: scatter packed edge record -------
__global__ void scatter_kernel(const int* __restrict__ src, const int* __restrict__ dst, int E, int N) {
    int i = blockIdx.x * blockDim.x + threadIdx.x;
    if (i < E) {
        int s = src[i];
        int p = atomicAdd(&g_cursor[dst[i]], 1);
        g_edge[p] = ((ULL)(unsigned)g_comb[s] << 32) | (unsigned)(s * 64);
    }
    if (i < N) g_cnt[i] = 0;
    if (i < 512) g_stats[i] = 0.f;
    if (i < 256) g_part[i] = 0u;
}

// ---------------- prep B1: small weight transposes ---------
__global__ void prep_kernel(const float* __restrict__ w0b,
                            const float* __restrict__ w1a, const float* __restrict__ w1b,
                            const float* __restrict__ w2a, const float* __restrict__ w2b,
                            const float* __restrict__ fc1w) {
    int j = blockIdx.x * 256 + threadIdx.x;
    if (j < 8192)  { int m = j >> 7, k = j & 127; g_wt0b[k * 64 + m] = w0b[j]; return; }
    if ((j -= 8192) < 4096)  { int m = j >> 6, k = j & 63; g_wt1a[k * 64 + m] = w1a[j]; return; }
    if ((j -= 4096) < 4096)  { int m = j >> 6, k = j & 63; g_wt1b[k * 64 + m] = w1b[j]; return; }
    if ((j -= 4096) < 4096)  { int m = j >> 6, k = j & 63; g_wt2a[k * 64 + m] = w2a[j]; return; }
    if ((j -= 4096) < 4096)  { int m = j >> 6, k = j & 63; g_wt2b[k * 64 + m] = w2b[j]; return; }
    if ((j -= 4096) < 20480) { int m = j / 320, k = j - m * 320; g_fc1t[k * 64 + m] = fc1w[j]; return; }
}

// ---------------- prep B2: T and U tables (tiled GEMM) -----
__global__ void __launch_bounds__(256) tables_kernel(
    const float* __restrict__ w0a, const float* __restrict__ fc1w,
    const float* __restrict__ ed, const float* __restrict__ el)
{
    extern __shared__ float smem[];
    float* A_s = smem;                   // 128*ASTRIDE
    float* W_s = smem + 128 * ASTRIDE;   // 32*132

    const int tid  = threadIdx.x;
    const bool isT = blockIdx.x < 16;
    const int c0   = (blockIdx.x & 15) * 64;
    const int M    = isT ? 128 : 64;
    const int ldW  = isT ? 128 : 320;
    const float* W = isT ? w0a : fc1w;

    for (int i = tid; i < 64 * 32; i += 256) {
        int cl = i >> 5, k4 = i & 31;
        int c = c0 + cl;
        const float* tbl = (k4 < 16) ? (ed + (c >> 4) * 64) : (el + (c & 15) * 64 - 64);
        float4 v = *(const float4*)&tbl[k4 * 4];
        A_s[(4 * k4 + 0) * ASTRIDE + cl] = v.x;
        A_s[(4 * k4 + 1) * ASTRIDE + cl] = v.y;
        A_s[(4 * k4 + 2) * ASTRIDE + cl] = v.z;
        A_s[(4 * k4 + 3) * ASTRIDE + cl] = v.w;
    }

    const int lane = tid & 31, wrp = tid >> 5;
    const int nb = wrp * 8;

    ULL acc[4][4];
#pragma unroll
    for (int i = 0; i < 4; i++)
#pragma unroll
        for (int p = 0; p < 4; p++) acc[i][p] = 0ULL;

    for (int kc = 0; kc < 4; kc++) {
        __syncthreads();
        for (int i = tid; i < 32 * M; i += 256) {
            int m = i >> 5, kk = i & 31;
            W_s[kk * 132 + m] = W[m * ldW + kc * 32 + kk];
        }
        __syncthreads();
#pragma unroll 8
        for (int kk = 0; kk < 32; kk++) {
            int k = kc * 32 + kk;
            const float* row = &A_s[k * ASTRIDE + nb];
            ulonglong2 n01 = *(const ulonglong2*)(row);
            ulonglong2 n23 = *(const ulonglong2*)(row + 4);
            ULL a0 = n01.x, a1 = n01.y, a2 = n23.x, a3 = n23.y;
            if (isT) {
                float4 w4 = *(const float4*)&W_s[kk * 132 + lane * 4];
                ULL w0 = pk2(w4.x, w4.x), w1 = pk2(w4.y, w4.y);
                ULL w2 = pk2(w4.z, w4.z), w3 = pk2(w4.w, w4.w);
                fma2(acc[0][0], w0, a0); fma2(acc[0][1], w0, a1); fma2(acc[0][2], w0, a2); fma2(acc[0][3], w0, a3);
                fma2(acc[1][0], w1, a0); fma2(acc[1][1], w1, a1); fma2(acc[1][2], w1, a2); fma2(acc[1][3], w1, a3);
                fma2(acc[2][0], w2, a0); fma2(acc[2][1], w2, a1); fma2(acc[2][2], w2, a2); fma2(acc[2][3], w2, a3);
                fma2(acc[3][0], w3, a0); fma2(acc[3][1], w3, a1); fma2(acc[3][2], w3, a2); fma2(acc[3][3], w3, a3);
            } else {
                float2 wv = *(const float2*)&W_s[kk * 132 + lane * 2];
                ULL w0 = pk2(wv.x, wv.x), w1 = pk2(wv.y, wv.y);
                fma2(acc[0][0], w0, a0); fma2(acc[0][1], w0, a1); fma2(acc[0][2], w0, a2); fma2(acc[0][3], w0, a3);
                fma2(acc[1][0], w1, a0); fma2(acc[1][1], w1, a1); fma2(acc[1][2], w1, a2); fma2(acc[1][3], w1, a3);
            }
        }
    }

#pragma unroll
    for (int p = 0; p < 4; p++) {
        int c = c0 + nb + 2 * p;
        if (isT) {
            float a0x, a0y, a1x, a1y, a2x, a2y, a3x, a3y;
            upk(acc[0][p], a0x, a0y); upk(acc[1][p], a1x, a1y);
            upk(acc[2][p], a2x, a2y); upk(acc[3][p], a3x, a3y);
            *(float4*)&g_T[c * 128 + lane * 4]       = make_float4(a0x, a1x, a2x, a3x);
            *(float4*)&g_T[(c + 1) * 128 + lane * 4] = make_float4(a0y, a1y, a2y, a3y);
        } else {
            float x0, x1, y0, y1;
            upk(acc[0][p], x0, x1); upk(acc[1][p], y0, y1);
            *(float2*)&g_U[c * 64 + lane * 2]       = make_float2(x0, y0);
            *(float2*)&g_U[(c + 1) * 64 + lane * 2] = make_float2(x1, y1);
        }
    }
}

// ---------------- layer-0 agg from T table (warp per node) ----------------
__global__ void agg0t_kernel(float* __restrict__ hout, int N) {
    int wid  = (blockIdx.x * blockDim.x + threadIdx.x) >> 5;
    int lane = threadIdx.x & 31;
    if (wid >= N) return;
    const int offi = lane * 4;
    float4 acc = *(const float4*)&g_T[g_comb[wid] + offi];
    int beg = g_rowptr[wid], end = g_rowptr[wid + 1];
    int e = beg;
    for (; e + 8 <= end; e += 8) {
        ULL e0 = g_edge[e],     e1 = g_edge[e + 1], e2 = g_edge[e + 2], e3 = g_edge[e + 3];
        ULL e4 = g_edge[e + 4], e5 = g_edge[e + 5], e6 = g_edge[e + 6], e7 = g_edge[e + 7];
        float4 v0 = *(const float4*)&g_T[(int)(e0 >> 32) + offi];
        float4 v1 = *(const float4*)&g_T[(int)(e1 >> 32) + offi];
        float4 v2 = *(const float4*)&g_T[(int)(e2 >> 32) + offi];
        float4 v3 = *(const float4*)&g_T[(int)(e3 >> 32) + offi];
        float4 v4 = *(const float4*)&g_T[(int)(e4 >> 32) + offi];
        float4 v5 = *(const float4*)&g_T[(int)(e5 >> 32) + offi];
        float4 v6 = *(const float4*)&g_T[(int)(e6 >> 32) + offi];
        float4 v7 = *(const float4*)&g_T[(int)(e7 >> 32) + offi];
        acc.x += ((v0.x + v1.x) + (v2.x + v3.x)) + ((v4.x + v5.x) + (v6.x + v7.x));
        acc.y += ((v0.y + v1.y) + (v2.y + v3.y)) + ((v4.y + v5.y) + (v6.y + v7.y));
        acc.z += ((v0.z + v1.z) + (v2.z + v3.z)) + ((v4.z + v5.z) + (v6.z + v7.z));
        acc.w += ((v0.w + v1.w) + (v2.w + v3.w)) + ((v4.w + v5.w) + (v6.w + v7.w));
    }
    for (; e < end; e++) {
        float4 v = *(const float4*)&g_T[(int)(g_edge[e] >> 32) + offi];
        acc.x += v.x; acc.y += v.y; acc.z += v.z; acc.w += v.w;
    }
    *(float4*)&hout[wid * 128 + offi] = acc;
}

// ---------------- layer-0 second GEMM: 128-node tiles ---------------------
__global__ void __launch_bounds__(256) mlp0b_kernel(
    const float* __restrict__ hin, const float* __restrict__ ba,
    const float* __restrict__ wtb, const float* __restrict__ bb,
    float* __restrict__ out, int N)
{
    extern __shared__ float smem[];
    float* A_s = smem;                    // 128*NSTRIDE
    float* RS  = smem + 128 * NSTRIDE;    // 512
    float* RQ  = RS + 512;                // 512

    const int tid = threadIdx.x;
    const int n0  = blockIdx.x * 128;

    for (int i = tid; i < 128 * 32; i += 256) {
        int nl = i >> 5, k4 = i & 31;
        int n = n0 + nl;
        float4 v = make_float4(0.f, 0.f, 0.f, 0.f);
        if (n < N) {
            v = *(const float4*)&hin[n * 128 + k4 * 4];
            float4 bv = *(const float4*)&ba[k4 * 4];
            v.x += bv.x; v.x = fmaxf(v.x, 0.01f * v.x);
            v.y += bv.y; v.y = fmaxf(v.y, 0.01f * v.y);
            v.z += bv.z; v.z = fmaxf(v.z, 0.01f * v.z);
            v.w += bv.w; v.w = fmaxf(v.w, 0.01f * v.w);
        }
        A_s[(4 * k4 + 0) * NSTRIDE + nl] = v.x;
        A_s[(4 * k4 + 1) * NSTRIDE + nl] = v.y;
        A_s[(4 * k4 + 2) * NSTRIDE + nl] = v.z;
        A_s[(4 * k4 + 3) * NSTRIDE + nl] = v.w;
    }
    __syncthreads();

    const int lane = tid & 31, wrp = tid >> 5;
    const int nb = wrp * 16;

    ULL cA[8], cB[8];
#pragma unroll
    for (int p = 0; p < 8; p++) { cA[p] = 0ULL; cB[p] = 0ULL; }
#pragma unroll 4
    for (int k = 0; k < 128; k++) {
        const float* row = &A_s[k * NSTRIDE + nb];
        float2 wv = *(const float2*)&wtb[k * 64 + lane * 2];
        ULL w0 = pk2(wv.x, wv.x), w1 = pk2(wv.y, wv.y);
        FMA_ROW(cA, cB, row, w0, w1);
    }
    float b0 = bb[lane * 2], b1 = bb[lane * 2 + 1];
    float s0 = 0.f, q0 = 0.f, s1 = 0.f, q1 = 0.f;
#pragma unroll
    for (int p = 0; p < 8; p++) {
        float x0, x1, y0, y1;
        upk(cA[p], x0, x1);
        upk(cB[p], y0, y1);
        int na = n0 + nb + 2 * p;
        if (na < N) {
            float o0 = x0 + b0, o1 = y0 + b1;
            *(float2*)&out[na * 64 + lane * 2] = make_float2(o0, o1);
            s0 += o0; q0 = fmaf(o0, o0, q0); s1 += o1; q1 = fmaf(o1, o1, q1);
        }
        if (na + 1 < N) {
            float o0 = x1 + b0, o1 = y1 + b1;
            *(float2*)&out[(na + 1) * 64 + lane * 2] = make_float2(o0, o1);
            s0 += o0; q0 = fmaf(o0, o0, q0); s1 += o1; q1 = fmaf(o1, o1, q1);
        }
    }
    RS[wrp * 64 + lane * 2] = s0; RS[wrp * 64 + lane * 2 + 1] = s1;
    RQ[wrp * 64 + lane * 2] = q0; RQ[wrp * 64 + lane * 2 + 1] = q1;
    __syncthreads();
    if (tid < 128) {
        int c = tid & 63;
        const float* P = (tid >= 64) ? RQ : RS;
        float v = 0.f;
#pragma unroll
        for (int w = 0; w < 8; w++) v += P[w * 64 + c];
        atomicAdd(&g_stats[((tid >= 64) ? 64 : 0) + c], v);
    }
}

// ---------------- aggregation with fused BN+lrelu (half-warp per node) ----
__global__ void aggbn_kernel(const float* __restrict__ pre,
                             const float* __restrict__ bnw, const float* __restrict__ bnb,
                             float* __restrict__ hout, int N, int bnidx) {
    __shared__ float sc[64], sh[64];
    if (threadIdx.x < 64) {
        int c = threadIdx.x;
        float m   = g_stats[bnidx * 128 + c] / (float)N;
        float var = g_stats[bnidx * 128 + 64 + c] / (float)N - m * m;
        float inv = rsqrtf(var + 1e-5f);
        float a   = bnw[c] * inv;
        sc[c] = a;
        sh[c] = bnb[c] - m * a;
    }
    __syncthreads();
    int hw   = (blockIdx.x * blockDim.x + threadIdx.x) >> 4;   // half-warp id = node
    int l16  = threadIdx.x & 15;
    if (hw >= N) return;
    const int li = l16 * 4;
    float4 a4 = *(const float4*)&sc[li];
    float4 c4 = *(const float4*)&sh[li];
#define BNR4(v) { v.x = fmaf(v.x, a4.x, c4.x); v.x = fmaxf(v.x, 0.01f * v.x); \
                  v.y = fmaf(v.y, a4.y, c4.y); v.y = fmaxf(v.y, 0.01f * v.y); \
                  v.z = fmaf(v.z, a4.z, c4.z); v.z = fmaxf(v.z, 0.01f * v.z); \
                  v.w = fmaf(v.w, a4.w, c4.w); v.w = fmaxf(v.w, 0.01f * v.w); }
    float4 acc = *(const float4*)&pre[hw * 64 + li];
    BNR4(acc);
    int beg = g_rowptr[hw], end = g_rowptr[hw + 1];
    int e = beg;
    for (; e + 8 <= end; e += 8) {
        ULL e0 = g_edge[e],     e1 = g_edge[e + 1], e2 = g_edge[e + 2], e3 = g_edge[e + 3];
        ULL e4 = g_edge[e + 4], e5 = g_edge[e + 5], e6 = g_edge[e + 6], e7 = g_edge[e + 7];
        float4 v0 = *(const float4*)&pre[(int)(unsigned)e0 + li];
        float4 v1 = *(const float4*)&pre[(int)(unsigned)e1 + li];
        float4 v2 = *(const float4*)&pre[(int)(unsigned)e2 + li];
        float4 v3 = *(const float4*)&pre[(int)(unsigned)e3 + li];
        float4 v4 = *(const float4*)&pre[(int)(unsigned)e4 + li];
        float4 v5 = *(const float4*)&pre[(int)(unsigned)e5 + li];
        float4 v6 = *(const float4*)&pre[(int)(unsigned)e6 + li];
        float4 v7 = *(const float4*)&pre[(int)(unsigned)e7 + li];
        BNR4(v0); BNR4(v1); BNR4(v2); BNR4(v3); BNR4(v4); BNR4(v5); BNR4(v6); BNR4(v7);
        acc.x += ((v0.x + v1.x) + (v2.x + v3.x)) + ((v4.x + v5.x) + (v6.x + v7.x));
        acc.y += ((v0.y + v1.y) + (v2.y + v3.y)) + ((v4.y + v5.y) + (v6.y + v7.y));
        acc.z += ((v0.z + v1.z) + (v2.z + v3.z)) + ((v4.z + v5.z) + (v6.z + v7.z));
        acc.w += ((v0.w + v1.w) + (v2.w + v3.w)) + ((v4.w + v5.w) + (v6.w + v7.w));
    }
    for (; e < end; e++) {
        float4 v = *(const float4*)&pre[(int)(unsigned)g_edge[e] + li];
        BNR4(v);
        acc.x += v.x; acc.y += v.y; acc.z += v.z; acc.w += v.w;
    }
#undef BNR4
    *(float4*)&hout[hw * 64 + li] = acc;
}

// ---------------- GIN MLP layers 1/2: 128-node tiles ----------------------
__global__ void __launch_bounds__(256) mlp_kernel(
    const float* __restrict__ hin,
    const float* __restrict__ wta, const float* __restrict__ ba,
    const float* __restrict__ wtb, const float* __restrict__ bb,
    float* __restrict__ out, int N, int bnidx)
{
    extern __shared__ float smem[];
    float* A_s = smem;                   // 64*NSTRIDE (reused for H)
    float* RS  = smem + 64 * NSTRIDE;    // 512
    float* RQ  = RS + 512;               // 512

    const int tid = threadIdx.x;
    const int n0  = blockIdx.x * 128;

    for (int i = tid; i < 128 * 16; i += 256) {
        int nl = i >> 4, k4 = i & 15;
        int n = n0 + nl;
        float4 v = make_float4(0.f, 0.f, 0.f, 0.f);
        if (n < N) v = *(const float4*)&hin[n * 64 + k4 * 4];
        A_s[(4 * k4 + 0) * NSTRIDE + nl] = v.x;
        A_s[(4 * k4 + 1) * NSTRIDE + nl] = v.y;
        A_s[(4 * k4 + 2) * NSTRIDE + nl] = v.z;
        A_s[(4 * k4 + 3) * NSTRIDE + nl] = v.w;
    }
    __syncthreads();

    const int lane = tid & 31, wrp = tid >> 5;
    const int nb = wrp * 16;

    // ---- GEMM1 ----
    ULL aA[8], aB[8];
#pragma unroll
    for (int p = 0; p < 8; p++) { aA[p] = 0ULL; aB[p] = 0ULL; }
#pragma unroll 4
    for (int k = 0; k < 64; k++) {
        const float* row = &A_s[k * NSTRIDE + nb];
        float2 wv = *(const float2*)&wta[k * 64 + lane * 2];
        ULL w0 = pk2(wv.x, wv.x), w1 = pk2(wv.y, wv.y);
        FMA_ROW(aA, aB, row, w0, w1);
    }

    __syncthreads();
    {
        float b0 = ba[lane * 2], b1 = ba[lane * 2 + 1];
        int m0 = lane * 2, m1 = lane * 2 + 1;
#pragma unroll
        for (int p = 0; p < 8; p++) {
            float x, y;
            upk(aA[p], x, y);
            x += b0; y += b0;
            x = fmaxf(x, 0.01f * x); y = fmaxf(y, 0.01f * y);
            *(ULL*)&A_s[m0 * NSTRIDE + nb + 2 * p] = pk2(x, y);
            upk(aB[p], x, y);
            x += b1; y += b1;
            x = fmaxf(x, 0.01f * x); y = fmaxf(y, 0.01f * y);
            *(ULL*)&A_s[m1 * NSTRIDE + nb + 2 * p] = pk2(x, y);
        }
    }
    __syncthreads();

    // ---- GEMM2 ----
    ULL cA[8], cB[8];
#pragma unroll
    for (int p = 0; p < 8; p++) { cA[p] = 0ULL; cB[p] = 0ULL; }
#pragma unroll 4
    for (int k = 0; k < 64; k++) {
        const float* row = &A_s[k * NSTRIDE + nb];
        float2 wv = *(const float2*)&wtb[k * 64 + lane * 2];
        ULL w0 = pk2(wv.x, wv.x), w1 = pk2(wv.y, wv.y);
        FMA_ROW(cA, cB, row, w0, w1);
    }
    float b0 = bb[lane * 2], b1 = bb[lane * 2 + 1];
    float s0 = 0.f, q0 = 0.f, s1 = 0.f, q1 = 0.f;
#pragma unroll
    for (int p = 0; p < 8; p++) {
        float x0, x1, y0, y1;
        upk(cA[p], x0, x1);
        upk(cB[p], y0, y1);
        int na = n0 + nb + 2 * p;
        if (na < N) {
            float o0 = x0 + b0, o1 = y0 + b1;
            *(float2*)&out[na * 64 + lane * 2] = make_float2(o0, o1);
            s0 += o0; q0 = fmaf(o0, o0, q0); s1 += o1; q1 = fmaf(o1, o1, q1);
        }
        if (na + 1 < N) {
            float o0 = x1 + b0, o1 = y1 + b1;
            *(float2*)&out[(na + 1) * 64 + lane * 2] = make_float2(o0, o1);
            s0 += o0; q0 = fmaf(o0, o0, q0); s1 += o1; q1 = fmaf(o1, o1, q1);
        }
    }
    RS[wrp * 64 + lane * 2] = s0; RS[wrp * 64 + lane * 2 + 1] = s1;
    RQ[wrp * 64 + lane * 2] = q0; RQ[wrp * 64 + lane * 2 + 1] = q1;
    __syncthreads();
    if (tid < 128) {
        int c = tid & 63;
        const float* P = (tid >= 64) ? RQ : RS;
        float v = 0.f;
#pragma unroll
        for (int w = 0; w < 8; w++) v += P[w * 64 + c];
        atomicAdd(&g_stats[bnidx * 128 + ((tid >= 64) ? 64 : 0) + c], v);
    }
}

// ---------------- fc1 head GEMM: 128-node tiles, K=192 + U-table ----------
__global__ void __launch_bounds__(256) fc1_kernel(
    const float* __restrict__ pre1, const float* __restrict__ pre2, const float* __restrict__ pre3,
    const float* __restrict__ bn0w, const float* __restrict__ bn0b,
    const float* __restrict__ bn1w, const float* __restrict__ bn1b,
    const float* __restrict__ bn2w, const float* __restrict__ bn2b,
    const float* __restrict__ fb,
    float* __restrict__ out, int N)
{
    extern __shared__ float smem[];
    float* A_s = smem;                      // 192*NSTRIDE
    float* RS  = A_s + 192 * NSTRIDE;       // 512
    float* RQ  = RS + 512;                  // 512
    float* sc  = RQ + 512;                  // 192
    float* sh  = sc + 192;                  // 192
    int*   s_comb = (int*)(sh + 192);       // 128

    const int tid = threadIdx.x;
    const int n0 = blockIdx.x * 128;
    if (tid < 192) {
        int l = tid >> 6, c = tid & 63;
        const float* w = (l == 0) ? bn0w : ((l == 1) ? bn1w : bn2w);
        const float* b = (l == 0) ? bn0b : ((l == 1) ? bn1b : bn2b);
        float m   = g_stats[l * 128 + c] / (float)N;
        float var = g_stats[l * 128 + 64 + c] / (float)N - m * m;
        float inv = rsqrtf(var + 1e-5f);
        float a   = w[c] * inv;
        sc[tid] = a;
        sh[tid] = b[c] - m * a;
    }
    if (tid >= 128) {
        int nl = tid - 128;
        int n = n0 + nl;
        s_comb[nl] = (n < N) ? (g_comb[n] >> 1) : 0;
    }
    if (tid < 128) {
        int n = n0 + tid;
        // defer: fill first half after barrier-free? No — separate predicate below.
    }
    __syncthreads();
    if (tid < 128) {
        // fill remaining s_comb entries 0..127? already covered by tid>=128 for nl in [0,128)
    }
    // NOTE: s_comb[0..127] filled by threads 128..255 above.

    for (int i = tid; i < 128 * 192; i += 256) {
        int nl = i / 192, k = i - nl * 192;
        int n = n0 + nl;
        float v = 0.f;
        if (n < N) {
            int l = k >> 6, c = k & 63;
            const float* pr = (l == 0) ? pre1 : ((l == 1) ? pre2 : pre3);
            float p = fmaf(pr[n * 64 + c], sc[k], sh[k]);
            v = fmaxf(p, 0.01f * p);
        }
        A_s[k * NSTRIDE + nl] = v;
    }
    __syncthreads();

    const int lane = tid & 31, wrp = tid >> 5;
    const int nb = wrp * 16;

    ULL cA[8], cB[8];
#pragma unroll
    for (int p = 0; p < 8; p++) { cA[p] = 0ULL; cB[p] = 0ULL; }
#pragma unroll 4
    for (int k = 0; k < 192; k++) {
        const float* row = &A_s[k * NSTRIDE + nb];
        float2 wv = *(const float2*)&g_fc1t[(128 + k) * 64 + lane * 2];
        ULL w0 = pk2(wv.x, wv.x), w1 = pk2(wv.y, wv.y);
        FMA_ROW(cA, cB, row, w0, w1);
    }

    float b0 = fb[lane * 2], b1 = fb[lane * 2 + 1];
    float s0 = 0.f, q0 = 0.f, s1 = 0.f, q1 = 0.f;
#pragma unroll
    for (int p = 0; p < 8; p++) {
        float x0, x1, y0, y1;
        upk(cA[p], x0, x1);
        upk(cB[p], y0, y1);
        int na = n0 + nb + 2 * p;
        if (na < N) {
            float2 uv = *(const float2*)&g_U[s_comb[nb + 2 * p] + lane * 2];
            float o0 = x0 + b0 + uv.x, o1 = y0 + b1 + uv.y;
            *(float2*)&out[na * 64 + lane * 2] = make_float2(o0, o1);
            s0 += o0; q0 = fmaf(o0, o0, q0); s1 += o1; q1 = fmaf(o1, o1, q1);
        }
        if (na + 1 < N) {
            float2 uv = *(const float2*)&g_U[s_comb[nb + 2 * p + 1] + lane * 2];
            float o0 = x1 + b0 + uv.x, o1 = y1 + b1 + uv.y;
            *(float2*)&out[(na + 1) * 64 + lane * 2] = make_float2(o0, o1);
            s0 += o0; q0 = fmaf(o0, o0, q0); s1 += o1; q1 = fmaf(o1, o1, q1);
        }
    }
    RS[wrp * 64 + lane * 2] = s0; RS[wrp * 64 + lane * 2 + 1] = s1;
    RQ[wrp * 64 + lane * 2] = q0; RQ[wrp * 64 + lane * 2 + 1] = q1;
    __syncthreads();
    if (tid < 128) {
        int c = tid & 63;
        const float* P = (tid >= 64) ? RQ : RS;
        float v = 0.f;
#pragma unroll
        for (int w = 0; w < 8; w++) v += P[w * 64 + c];
        atomicAdd(&g_stats[3 * 128 + ((tid >= 64) ? 64 : 0) + c], v);
    }
}

// ---------------- final head ----------------
__global__ void final_kernel(const float* __restrict__ hpre,
                             const float* __restrict__ bnw, const float* __restrict__ bnb,
                             const float* __restrict__ fc2w, const float* __restrict__ fc2b,
                             float* __restrict__ out, int N) {
    __shared__ float sc[64], sh[64], w2s[64];
    if (threadIdx.x < 64) {
        int c = threadIdx.x;
        float m   = g_stats[3 * 128 + c] / (float)N;
        float var = g_stats[3 * 128 + 64 + c] / (float)N - m * m;
        float inv = rsqrtf(var + 1e-5f);
        float a   = bnw[c] * inv;
        sc[c]  = a;
        sh[c]  = bnb[c] - m * a;
        w2s[c] = fc2w[c];
    }
    __syncthreads();
    int wid  = (blockIdx.x * blockDim.x + threadIdx.x) >> 5;
    int lane = threadIdx.x & 31;
    if (wid >= N) return;
    float2 v = *(const float2*)&hpre[wid * 64 + lane * 2];
    float x = fmaf(v.x, sc[lane * 2], sh[lane * 2]);         x = fmaxf(x, 0.01f * x);
    float y = fmaf(v.y, sc[lane * 2 + 1], sh[lane * 2 + 1]); y = fmaxf(y, 0.01f * y);
    float acc = fmaf(x, w2s[lane * 2], y * w2s[lane * 2 + 1]);
#pragma unroll
    for (int off = 16; off; off >>= 1) acc += __shfl_xor_sync(0xffffffffu, acc, off);
    if (lane == 0) out[wid] = 1.f / (1.f + expf(-(acc + fc2b[0])));
}

// ---------------- launch ----------------
extern "C" void kernel_launch(void* const* d_in, const int* in_sizes, int n_in,
                              void* d_out, int out_size) {
    const float* emb_deg = (const float*)d_in[0];
    const float* emb_lab = (const float*)d_in[1];
    const float* w0a = (const float*)d_in[2];  const float* b0a = (const float*)d_in[3];
    const float* w0b = (const float*)d_in[4];  const float* b0b = (const float*)d_in[5];
    const float* bn0w = (const float*)d_in[6]; const float* bn0b = (const float*)d_in[7];
    const float* w1a = (const float*)d_in[8];  const float* b1a = (const float*)d_in[9];
    const float* w1b = (const float*)d_in[10]; const float* b1b = (const float*)d_in[11];
    const float* bn1w = (const float*)d_in[12]; const float* bn1b = (const float*)d_in[13];
    const float* w2a = (const float*)d_in[14]; const float* b2a = (const float*)d_in[15];
    const float* w2b = (const float*)d_in[16]; const float* b2b = (const float*)d_in[17];
    const float* bn2w = (const float*)d_in[18]; const float* bn2b = (const float*)d_in[19];
    const float* fc1w = (const float*)d_in[20]; const float* fc1b = (const float*)d_in[21];
    const float* fcbnw = (const float*)d_in[22]; const float* fcbnb = (const float*)d_in[23];
    const float* fc2w = (const float*)d_in[24]; const float* fc2b = (const float*)d_in[25];
    const int* node_deg = (const int*)d_in[26];
    const int* node_lab = (const int*)d_in[27];
    const int* edge = (const int*)d_in[28];

    const int N = in_sizes[26];
    const int E = in_sizes[28] / 2;
    const int* src  = edge;
    const int* dstp = edge + E;
    float* out = (float*)d_out;

    float *hin, *pre1, *pre2, *pre3, *pre4;
    float *wt0b, *wt1a, *wt1b, *wt2a, *wt2b;
    cudaGetSymbolAddress((void**)&hin,  g_hin);
    cudaGetSymbolAddress((void**)&pre1, g_pre1);
    cudaGetSymbolAddress((void**)&pre2, g_pre2);
    cudaGetSymbolAddress((void**)&pre3, g_pre3);
    cudaGetSymbolAddress((void**)&pre4, g_pre4);
    cudaGetSymbolAddress((void**)&wt0b, g_wt0b);
    cudaGetSymbolAddress((void**)&wt1a, g_wt1a);
    cudaGetSymbolAddress((void**)&wt1b, g_wt1b);
    cudaGetSymbolAddress((void**)&wt2a, g_wt2a);
    cudaGetSymbolAddress((void**)&wt2b, g_wt2b);

    const int TB = 256;
    const int mlpBlocks  = (N + 127) / 128;
    const int warpBlocks = (N * 32 + TB - 1) / TB;
    const int hwBlocks   = (N * 16 + TB - 1) / TB;
    const int scanBlocks = (N + 255) / 256;
    const int prepBlocks = (45056 + 255) / 256;

    const int SM_TBL   = (128 * ASTRIDE + 32 * 132) * 4;             // 51712
    const int SM_MLP0B = (128 * NSTRIDE + 1024) * 4;                 // 71680
    const int SM_MLP1  = (64 * NSTRIDE + 1024) * 4;                  // 37888
    const int SM_FC1   = (192 * NSTRIDE + 1024 + 384 + 128) * 4;     // 107520
    cudaFuncSetAttribute(tables_kernel, cudaFuncAttributeMaxDynamicSharedMemorySize, SM_TBL);
    cudaFuncSetAttribute(mlp0b_kernel,  cudaFuncAttributeMaxDynamicSharedMemorySize, SM_MLP0B);
    cudaFuncSetAttribute(mlp_kernel,    cudaFuncAttributeMaxDynamicSharedMemorySize, SM_MLP1);
    cudaFuncSetAttribute(fc1_kernel,    cudaFuncAttributeMaxDynamicSharedMemorySize, SM_FC1);

    static cudaStream_t sPrep = []() {
        cudaStream_t s; cudaStreamCreateWithFlags(&s, cudaStreamNonBlocking); return s;
    }();
    static cudaEvent_t evFork = []() {
        cudaEvent_t e; cudaEventCreateWithFlags(&e, cudaEventDisableTiming); return e;
    }();
    static cudaEvent_t evJoin = []() {
        cudaEvent_t e; cudaEventCreateWithFlags(&e, cudaEventDisableTiming); return e;
    }();

    // fork: prep branch on side stream
    cudaEventRecord(evFork, 0);
    cudaStreamWaitEvent(sPrep, evFork, 0);
    prep_kernel<<<prepBlocks, 256, 0, sPrep>>>(w0b, w1a, w1b, w2a, w2b, fc1w);
    tables_kernel<<<32, 256, SM_TBL, sPrep>>>(w0a, fc1w, emb_deg, emb_lab);
    cudaEventRecord(evJoin, sPrep);

    // CSR branch on main stream
    hist_kernel<<<(E + TB - 1) / TB, TB>>>(dstp, node_deg, node_lab, E, N);
    scan_kernel<<<scanBlocks, 256>>>(N);
    scatter_kernel<<<(E + TB - 1) / TB, TB>>>(src, dstp, E, N);

    // join
    cudaStreamWaitEvent(0, evJoin, 0);

    // layer 0
    agg0t_kernel<<<warpBlocks, TB>>>(hin, N);
    mlp0b_kernel<<<mlpBlocks, 256, SM_MLP0B>>>(hin, b0a, wt0b, b0b, pre1, N);

    // layer 1
    aggbn_kernel<<<hwBlocks, TB>>>(pre1, bn0w, bn0b, hin, N, 0);
    mlp_kernel<<<mlpBlocks, 256, SM_MLP1>>>(hin, wt1a, b1a, wt1b, b1b, pre2, N, 1);

    // layer 2
    aggbn_kernel<<<hwBlocks, TB>>>(pre2, bn1w, bn1b, hin, N, 1);
    mlp_kernel<<<mlpBlocks, 256, SM_MLP1>>>(hin, wt2a, b2a, wt2b, b2b, pre3, N, 2);

    // head
    fc1_kernel<<<mlpBlocks, 256, SM_FC1>>>(pre1, pre2, pre3,
                                           bn0w, bn0b, bn1w, bn1b, bn2w, bn2b,
                                           fc1b, pre4, N);
    final_kernel<<<warpBlocks, TB>>>(pre4, fcbnw, fcbnb, fc2w, fc2b, out, N);
}

// round 15
// speedup vs baseline: 1.0825x; 1.0825x over previous
#include <cuda_runtime.h>
#include <math.h>

#define NN 50000
#define NE 800000
typedef unsigned long long ULL;

// ---------------- device scratch ----------------
__device__ float g_hin [NN * 128];
__device__ float g_pre1[NN * 64];
__device__ float g_pre2[NN * 64];
__device__ float g_pre3[NN * 64];
__device__ float g_pre4[NN * 64];
__device__ float g_wt0b[128 * 64];
__device__ float g_wt1a[64 * 64];
__device__ float g_wt1b[64 * 64];
__device__ float g_wt2a[64 * 64];
__device__ float g_wt2b[64 * 64];
__device__ float g_fc1t[320 * 64];
__device__ float g_U[1024 * 64];     // U[c][m] = x0_c @ fc1_w[:, :128]^T
__device__ float g_T[1024 * 128];    // T[c][m] = x0_c @ w0a^T
__device__ int   g_comb[NN];         // (deg*16+lab)*128
__device__ int   g_cnt[NN];
__device__ int   g_rowptr[NN + 1];
__device__ int   g_cursor[NN];
__device__ ULL   g_edge[NE];         // lo32 = src*64, hi32 = comb
__device__ unsigned int g_part[256];
__device__ float g_stats[4 * 128];

#define ASTRIDE 68   // floats per smem row: 16B-aligned -> LDS.128

// ---------------- f32x2 helpers ----------------
__device__ __forceinline__ ULL pk2(float x, float y) {
    ULL r; asm("mov.b64 %0, {%1,%2};" : "=l"(r) : "f"(x), "f"(y)); return r;
}
__device__ __forceinline__ void upk(ULL v, float& x, float& y) {
    asm("mov.b64 {%0,%1}, %2;" : "=f"(x), "=f"(y) : "l"(v));
}
__device__ __forceinline__ void fma2(ULL& d, ULL a, ULL b) {
    asm("fma.rn.f32x2 %0, %1, %2, %0;" : "+l"(d) : "l"(a), "l"(b));
}

// ---------------- CSR A1: histogram by dst + comb ----------
__global__ void hist_kernel(const int* __restrict__ dst,
                            const int* __restrict__ ndeg, const int* __restrict__ nlab,
                            int E, int N) {
    int i = blockIdx.x * blockDim.x + threadIdx.x;
    if (i < E) atomicAdd(&g_cnt[dst[i]], 1);
    if (i < N) g_comb[i] = (ndeg[i] * 16 + nlab[i]) << 7;
}

// ---------------- CSR A2: decoupled-lookback scan ----------
__global__ void scan_kernel(int N) {
    __shared__ int sm[256];
    __shared__ int s_base;
    const int b = blockIdx.x;
    const int t = threadIdx.x;
    int idx = b * 256 + t;
    int v = (idx < N) ? g_cnt[idx] : 0;
    sm[t] = v;
    __syncthreads();
    for (int o = 1; o < 256; o <<= 1) {
        int u = (t >= o) ? sm[t - o] : 0;
        __syncthreads(); sm[t] += u; __syncthreads();
    }
    if (t == 255) {
        int total = sm[255];
        if (b == 0) {
            atomicExch(&g_part[0], 0x80000000u | (unsigned)total);
            s_base = 0;
        } else {
            atomicExch(&g_part[b], 0x40000000u | (unsigned)total);
            int excl = 0;
            for (int p = b - 1;;) {
                unsigned pv;
                do { pv = atomicAdd(&g_part[p], 0u); } while (pv < 0x40000000u);
                excl += (int)(pv & 0x3FFFFFFFu);
                if (pv >= 0x80000000u) break;
                p--;
            }
            atomicExch(&g_part[b], 0x80000000u | (unsigned)(excl + total));
            s_base = excl;
        }
    }
    __syncthreads();
    int excl_local = sm[t] - v + s_base;
    if (idx < N) {
        g_rowptr[idx] = excl_local;
        g_cursor[idx] = excl_local;
        if (idx == N - 1) g_rowptr[N] = excl_local + v;
    }
}

// ---------------- CSR A3: scatter packed edge record -------
__global__ void scatter_kernel(const int* __restrict__ src, const int* __restrict__ dst, int E, int N) {
    int i = blockIdx.x * blockDim.x + threadIdx.x;
    if (i < E) {
        int s = src[i];
        int p = atomicAdd(&g_cursor[dst[i]], 1);
        g_edge[p] = ((ULL)(unsigned)g_comb[s] << 32) | (unsigned)(s * 64);
    }
    if (i < N) g_cnt[i] = 0;
    if (i < 512) g_stats[i] = 0.f;
    if (i < 256) g_part[i] = 0u;
}

// ---------------- prep B1: small weight transposes ---------
__global__ void prep_kernel(const float* __restrict__ w0b,
                            const float* __restrict__ w1a, const float* __restrict__ w1b,
                            const float* __restrict__ w2a, const float* __restrict__ w2b,
                            const float* __restrict__ fc1w) {
    int j = blockIdx.x * 256 + threadIdx.x;
    if (j < 8192)  { int m = j >> 7, k = j & 127; g_wt0b[k * 64 + m] = w0b[j]; return; }
    if ((j -= 8192) < 4096)  { int m = j >> 6, k = j & 63; g_wt1a[k * 64 + m] = w1a[j]; return; }
    if ((j -= 4096) < 4096)  { int m = j >> 6, k = j & 63; g_wt1b[k * 64 + m] = w1b[j]; return; }
    if ((j -= 4096) < 4096)  { int m = j >> 6, k = j & 63; g_wt2a[k * 64 + m] = w2a[j]; return; }
    if ((j -= 4096) < 4096)  { int m = j >> 6, k = j & 63; g_wt2b[k * 64 + m] = w2b[j]; return; }
    if ((j -= 4096) < 20480) { int m = j / 320, k = j - m * 320; g_fc1t[k * 64 + m] = fc1w[j]; return; }
}

// ---------------- prep B2: T and U tables (tiled GEMM) -----
__global__ void __launch_bounds__(256) tables_kernel(
    const float* __restrict__ w0a, const float* __restrict__ fc1w,
    const float* __restrict__ ed, const float* __restrict__ el)
{
    extern __shared__ float smem[];
    float* A_s = smem;                   // 128*ASTRIDE
    float* W_s = smem + 128 * ASTRIDE;   // 32*132

    const int tid  = threadIdx.x;
    const bool isT = blockIdx.x < 16;
    const int c0   = (blockIdx.x & 15) * 64;
    const int M    = isT ? 128 : 64;
    const int ldW  = isT ? 128 : 320;
    const float* W = isT ? w0a : fc1w;

    for (int i = tid; i < 64 * 32; i += 256) {
        int cl = i >> 5, k4 = i & 31;
        int c = c0 + cl;
        const float* tbl = (k4 < 16) ? (ed + (c >> 4) * 64) : (el + (c & 15) * 64 - 64);
        float4 v = *(const float4*)&tbl[k4 * 4];
        A_s[(4 * k4 + 0) * ASTRIDE + cl] = v.x;
        A_s[(4 * k4 + 1) * ASTRIDE + cl] = v.y;
        A_s[(4 * k4 + 2) * ASTRIDE + cl] = v.z;
        A_s[(4 * k4 + 3) * ASTRIDE + cl] = v.w;
    }

    const int lane = tid & 31, wrp = tid >> 5;
    const int nb = wrp * 8;

    ULL acc[4][4];
#pragma unroll
    for (int i = 0; i < 4; i++)
#pragma unroll
        for (int p = 0; p < 4; p++) acc[i][p] = 0ULL;

    for (int kc = 0; kc < 4; kc++) {
        __syncthreads();
        for (int i = tid; i < 32 * M; i += 256) {
            int m = i >> 5, kk = i & 31;
            W_s[kk * 132 + m] = W[m * ldW + kc * 32 + kk];
        }
        __syncthreads();
#pragma unroll 8
        for (int kk = 0; kk < 32; kk++) {
            int k = kc * 32 + kk;
            const float* row = &A_s[k * ASTRIDE + nb];
            ulonglong2 n01 = *(const ulonglong2*)(row);
            ulonglong2 n23 = *(const ulonglong2*)(row + 4);
            ULL a0 = n01.x, a1 = n01.y, a2 = n23.x, a3 = n23.y;
            if (isT) {
                float4 w4 = *(const float4*)&W_s[kk * 132 + lane * 4];
                ULL w0 = pk2(w4.x, w4.x), w1 = pk2(w4.y, w4.y);
                ULL w2 = pk2(w4.z, w4.z), w3 = pk2(w4.w, w4.w);
                fma2(acc[0][0], w0, a0); fma2(acc[0][1], w0, a1); fma2(acc[0][2], w0, a2); fma2(acc[0][3], w0, a3);
                fma2(acc[1][0], w1, a0); fma2(acc[1][1], w1, a1); fma2(acc[1][2], w1, a2); fma2(acc[1][3], w1, a3);
                fma2(acc[2][0], w2, a0); fma2(acc[2][1], w2, a1); fma2(acc[2][2], w2, a2); fma2(acc[2][3], w2, a3);
                fma2(acc[3][0], w3, a0); fma2(acc[3][1], w3, a1); fma2(acc[3][2], w3, a2); fma2(acc[3][3], w3, a3);
            } else {
                float2 wv = *(const float2*)&W_s[kk * 132 + lane * 2];
                ULL w0 = pk2(wv.x, wv.x), w1 = pk2(wv.y, wv.y);
                fma2(acc[0][0], w0, a0); fma2(acc[0][1], w0, a1); fma2(acc[0][2], w0, a2); fma2(acc[0][3], w0, a3);
                fma2(acc[1][0], w1, a0); fma2(acc[1][1], w1, a1); fma2(acc[1][2], w1, a2); fma2(acc[1][3], w1, a3);
            }
        }
    }

#pragma unroll
    for (int p = 0; p < 4; p++) {
        int c = c0 + nb + 2 * p;
        if (isT) {
            float a0x, a0y, a1x, a1y, a2x, a2y, a3x, a3y;
            upk(acc[0][p], a0x, a0y); upk(acc[1][p], a1x, a1y);
            upk(acc[2][p], a2x, a2y); upk(acc[3][p], a3x, a3y);
            *(float4*)&g_T[c * 128 + lane * 4]       = make_float4(a0x, a1x, a2x, a3x);
            *(float4*)&g_T[(c + 1) * 128 + lane * 4] = make_float4(a0y, a1y, a2y, a3y);
        } else {
            float x0, x1, y0, y1;
            upk(acc[0][p], x0, x1); upk(acc[1][p], y0, y1);
            *(float2*)&g_U[c * 64 + lane * 2]       = make_float2(x0, y0);
            *(float2*)&g_U[(c + 1) * 64 + lane * 2] = make_float2(x1, y1);
        }
    }
}

// ---------------- layer-0 agg from T table (warp per node) ----------------
__global__ void agg0t_kernel(float* __restrict__ hout, int N) {
    int wid  = (blockIdx.x * blockDim.x + threadIdx.x) >> 5;
    int lane = threadIdx.x & 31;
    if (wid >= N) return;
    const int offi = lane * 4;
    float4 acc = *(const float4*)&g_T[g_comb[wid] + offi];
    int beg = g_rowptr[wid], end = g_rowptr[wid + 1];
    int e = beg;
    for (; e + 8 <= end; e += 8) {
        ULL e0 = g_edge[e],     e1 = g_edge[e + 1], e2 = g_edge[e + 2], e3 = g_edge[e + 3];
        ULL e4 = g_edge[e + 4], e5 = g_edge[e + 5], e6 = g_edge[e + 6], e7 = g_edge[e + 7];
        float4 v0 = *(const float4*)&g_T[(int)(e0 >> 32) + offi];
        float4 v1 = *(const float4*)&g_T[(int)(e1 >> 32) + offi];
        float4 v2 = *(const float4*)&g_T[(int)(e2 >> 32) + offi];
        float4 v3 = *(const float4*)&g_T[(int)(e3 >> 32) + offi];
        float4 v4 = *(const float4*)&g_T[(int)(e4 >> 32) + offi];
        float4 v5 = *(const float4*)&g_T[(int)(e5 >> 32) + offi];
        float4 v6 = *(const float4*)&g_T[(int)(e6 >> 32) + offi];
        float4 v7 = *(const float4*)&g_T[(int)(e7 >> 32) + offi];
        acc.x += ((v0.x + v1.x) + (v2.x + v3.x)) + ((v4.x + v5.x) + (v6.x + v7.x));
        acc.y += ((v0.y + v1.y) + (v2.y + v3.y)) + ((v4.y + v5.y) + (v6.y + v7.y));
        acc.z += ((v0.z + v1.z) + (v2.z + v3.z)) + ((v4.z + v5.z) + (v6.z + v7.z));
        acc.w += ((v0.w + v1.w) + (v2.w + v3.w)) + ((v4.w + v5.w) + (v6.w + v7.w));
    }
    for (; e < end; e++) {
        float4 v = *(const float4*)&g_T[(int)(g_edge[e] >> 32) + offi];
        acc.x += v.x; acc.y += v.y; acc.z += v.z; acc.w += v.w;
    }
    *(float4*)&hout[wid * 128 + offi] = acc;
}

// ---------------- layer-0 second GEMM (64-node tiles, R13 form) -----------
__global__ void __launch_bounds__(256) mlp0b_kernel(
    const float* __restrict__ hin, const float* __restrict__ ba,
    const float* __restrict__ wtb, const float* __restrict__ bb,
    float* __restrict__ out, int N)
{
    extern __shared__ float smem[];
    float* A_s = smem;                    // 128*ASTRIDE
    float* RS  = smem + 128 * ASTRIDE;    // 512
    float* RQ  = RS + 512;                // 512

    const int tid = threadIdx.x;
    const int n0  = blockIdx.x * 64;

    for (int i = tid; i < 64 * 32; i += 256) {
        int nl = i >> 5, k4 = i & 31;
        int n = n0 + nl;
        float4 v = make_float4(0.f, 0.f, 0.f, 0.f);
        if (n < N) {
            v = *(const float4*)&hin[n * 128 + k4 * 4];
            float4 bv = *(const float4*)&ba[k4 * 4];
            v.x += bv.x; v.x = fmaxf(v.x, 0.01f * v.x);
            v.y += bv.y; v.y = fmaxf(v.y, 0.01f * v.y);
            v.z += bv.z; v.z = fmaxf(v.z, 0.01f * v.z);
            v.w += bv.w; v.w = fmaxf(v.w, 0.01f * v.w);
        }
        A_s[(4 * k4 + 0) * ASTRIDE + nl] = v.x;
        A_s[(4 * k4 + 1) * ASTRIDE + nl] = v.y;
        A_s[(4 * k4 + 2) * ASTRIDE + nl] = v.z;
        A_s[(4 * k4 + 3) * ASTRIDE + nl] = v.w;
    }
    __syncthreads();

    const int lane = tid & 31, wrp = tid >> 5;
    const int nb = wrp * 8;

    ULL c2[2][4];
#pragma unroll
    for (int i = 0; i < 2; i++)
#pragma unroll
        for (int p = 0; p < 4; p++) c2[i][p] = 0ULL;
#pragma unroll 8
    for (int k = 0; k < 128; k++) {
        const float* row = &A_s[k * ASTRIDE + nb];
        ulonglong2 n01 = *(const ulonglong2*)(row);
        ulonglong2 n23 = *(const ulonglong2*)(row + 4);
        ULL a0 = n01.x, a1 = n01.y, a2 = n23.x, a3 = n23.y;
        float2 wv = *(const float2*)&wtb[k * 64 + lane * 2];
        ULL w0 = pk2(wv.x, wv.x), w1 = pk2(wv.y, wv.y);
        fma2(c2[0][0], w0, a0); fma2(c2[0][1], w0, a1); fma2(c2[0][2], w0, a2); fma2(c2[0][3], w0, a3);
        fma2(c2[1][0], w1, a0); fma2(c2[1][1], w1, a1); fma2(c2[1][2], w1, a2); fma2(c2[1][3], w1, a3);
    }
    float b0 = bb[lane * 2], b1 = bb[lane * 2 + 1];
    float s0 = 0.f, q0 = 0.f, s1 = 0.f, q1 = 0.f;
#pragma unroll
    for (int p = 0; p < 4; p++) {
        float x0, x1, y0, y1;
        upk(c2[0][p], x0, x1);
        upk(c2[1][p], y0, y1);
        int na = n0 + nb + 2 * p;
        if (na < N) {
            float o0 = x0 + b0, o1 = y0 + b1;
            *(float2*)&out[na * 64 + lane * 2] = make_float2(o0, o1);
            s0 += o0; q0 = fmaf(o0, o0, q0); s1 += o1; q1 = fmaf(o1, o1, q1);
        }
        if (na + 1 < N) {
            float o0 = x1 + b0, o1 = y1 + b1;
            *(float2*)&out[(na + 1) * 64 + lane * 2] = make_float2(o0, o1);
            s0 += o0; q0 = fmaf(o0, o0, q0); s1 += o1; q1 = fmaf(o1, o1, q1);
        }
    }
    RS[wrp * 64 + lane * 2] = s0; RS[wrp * 64 + lane * 2 + 1] = s1;
    RQ[wrp * 64 + lane * 2] = q0; RQ[wrp * 64 + lane * 2 + 1] = q1;
    __syncthreads();
    if (tid < 128) {
        int c = tid & 63;
        const float* P = (tid >= 64) ? RQ : RS;
        float v = 0.f;
#pragma unroll
        for (int w = 0; w < 8; w++) v += P[w * 64 + c];
        atomicAdd(&g_stats[((tid >= 64) ? 64 : 0) + c], v);
    }
}

// ---------------- aggregation fused BN+lrelu (half-warp per node) ---------
__global__ void aggbn_kernel(const float* __restrict__ pre,
                             const float* __restrict__ bnw, const float* __restrict__ bnb,
                             float* __restrict__ hout, int N, int bnidx) {
    __shared__ float sc[64], sh[64];
    if (threadIdx.x < 64) {
        int c = threadIdx.x;
        float m   = g_stats[bnidx * 128 + c] / (float)N;
        float var = g_stats[bnidx * 128 + 64 + c] / (float)N - m * m;
        float inv = rsqrtf(var + 1e-5f);
        float a   = bnw[c] * inv;
        sc[c] = a;
        sh[c] = bnb[c] - m * a;
    }
    __syncthreads();
    int hw  = (blockIdx.x * blockDim.x + threadIdx.x) >> 4;   // half-warp = node
    int l16 = threadIdx.x & 15;
    if (hw >= N) return;
    const int li = l16 * 4;
    float4 a4 = *(const float4*)&sc[li];
    float4 c4 = *(const float4*)&sh[li];
#define BNR4(v) { v.x = fmaf(v.x, a4.x, c4.x); v.x = fmaxf(v.x, 0.01f * v.x); \
                  v.y = fmaf(v.y, a4.y, c4.y); v.y = fmaxf(v.y, 0.01f * v.y); \
                  v.z = fmaf(v.z, a4.z, c4.z); v.z = fmaxf(v.z, 0.01f * v.z); \
                  v.w = fmaf(v.w, a4.w, c4.w); v.w = fmaxf(v.w, 0.01f * v.w); }
    float4 acc = *(const float4*)&pre[hw * 64 + li];
    BNR4(acc);
    int beg = g_rowptr[hw], end = g_rowptr[hw + 1];
    int e = beg;
    for (; e + 8 <= end; e += 8) {
        ULL e0 = g_edge[e],     e1 = g_edge[e + 1], e2 = g_edge[e + 2], e3 = g_edge[e + 3];
        ULL e4 = g_edge[e + 4], e5 = g_edge[e + 5], e6 = g_edge[e + 6], e7 = g_edge[e + 7];
        float4 v0 = *(const float4*)&pre[(int)(unsigned)e0 + li];
        float4 v1 = *(const float4*)&pre[(int)(unsigned)e1 + li];
        float4 v2 = *(const float4*)&pre[(int)(unsigned)e2 + li];
        float4 v3 = *(const float4*)&pre[(int)(unsigned)e3 + li];
        float4 v4 = *(const float4*)&pre[(int)(unsigned)e4 + li];
        float4 v5 = *(const float4*)&pre[(int)(unsigned)e5 + li];
        float4 v6 = *(const float4*)&pre[(int)(unsigned)e6 + li];
        float4 v7 = *(const float4*)&pre[(int)(unsigned)e7 + li];
        BNR4(v0); BNR4(v1); BNR4(v2); BNR4(v3); BNR4(v4); BNR4(v5); BNR4(v6); BNR4(v7);
        acc.x += ((v0.x + v1.x) + (v2.x + v3.x)) + ((v4.x + v5.x) + (v6.x + v7.x));
        acc.y += ((v0.y + v1.y) + (v2.y + v3.y)) + ((v4.y + v5.y) + (v6.y + v7.y));
        acc.z += ((v0.z + v1.z) + (v2.z + v3.z)) + ((v4.z + v5.z) + (v6.z + v7.z));
        acc.w += ((v0.w + v1.w) + (v2.w + v3.w)) + ((v4.w + v5.w) + (v6.w + v7.w));
    }
    for (; e < end; e++) {
        float4 v = *(const float4*)&pre[(int)(unsigned)g_edge[e] + li];
        BNR4(v);
        acc.x += v.x; acc.y += v.y; acc.z += v.z; acc.w += v.w;
    }
#undef BNR4
    *(float4*)&hout[hw * 64 + li] = acc;
}

// ---------------- GIN MLP layers 1/2 (64-node tiles, R13 form) ------------
__global__ void __launch_bounds__(256) mlp_kernel(
    const float* __restrict__ hin,
    const float* __restrict__ wta, const float* __restrict__ ba,
    const float* __restrict__ wtb, const float* __restrict__ bb,
    float* __restrict__ out, int N, int bnidx)
{
    extern __shared__ float smem[];
    float* A_s = smem;                   // 64*ASTRIDE (reused for H)
    float* RS  = smem + 64 * ASTRIDE;    // 512
    float* RQ  = RS + 512;               // 512

    const int tid = threadIdx.x;
    const int n0  = blockIdx.x * 64;

    for (int i = tid; i < 64 * 16; i += 256) {
        int nl = i >> 4, k4 = i & 15;
        int n = n0 + nl;
        float4 v = make_float4(0.f, 0.f, 0.f, 0.f);
        if (n < N) v = *(const float4*)&hin[n * 64 + k4 * 4];
        A_s[(4 * k4 + 0) * ASTRIDE + nl] = v.x;
        A_s[(4 * k4 + 1) * ASTRIDE + nl] = v.y;
        A_s[(4 * k4 + 2) * ASTRIDE + nl] = v.z;
        A_s[(4 * k4 + 3) * ASTRIDE + nl] = v.w;
    }
    __syncthreads();

    const int lane = tid & 31, wrp = tid >> 5;
    const int nb = wrp * 8;

    ULL acc[2][4];
#pragma unroll
    for (int i = 0; i < 2; i++)
#pragma unroll
        for (int p = 0; p < 4; p++) acc[i][p] = 0ULL;
#pragma unroll 8
    for (int k = 0; k < 64; k++) {
        const float* row = &A_s[k * ASTRIDE + nb];
        ulonglong2 n01 = *(const ulonglong2*)(row);
        ulonglong2 n23 = *(const ulonglong2*)(row + 4);
        ULL a0 = n01.x, a1 = n01.y, a2 = n23.x, a3 = n23.y;
        float2 wv = *(const float2*)&wta[k * 64 + lane * 2];
        ULL w0 = pk2(wv.x, wv.x), w1 = pk2(wv.y, wv.y);
        fma2(acc[0][0], w0, a0); fma2(acc[0][1], w0, a1); fma2(acc[0][2], w0, a2); fma2(acc[0][3], w0, a3);
        fma2(acc[1][0], w1, a0); fma2(acc[1][1], w1, a1); fma2(acc[1][2], w1, a2); fma2(acc[1][3], w1, a3);
    }

    __syncthreads();
#pragma unroll
    for (int i = 0; i < 2; i++) {
        int m = lane * 2 + i;
        float bv = ba[m];
#pragma unroll
        for (int p = 0; p < 4; p++) {
            float x, y; upk(acc[i][p], x, y);
            x += bv; y += bv;
            x = fmaxf(x, 0.01f * x); y = fmaxf(y, 0.01f * y);
            *(ULL*)&A_s[m * ASTRIDE + nb + 2 * p] = pk2(x, y);
        }
    }
    __syncthreads();

    ULL c2[2][4];
#pragma unroll
    for (int i = 0; i < 2; i++)
#pragma unroll
        for (int p = 0; p < 4; p++) c2[i][p] = 0ULL;
#pragma unroll 8
    for (int k = 0; k < 64; k++) {
        const float* row = &A_s[k * ASTRIDE + nb];
        ulonglong2 n01 = *(const ulonglong2*)(row);
        ulonglong2 n23 = *(const ulonglong2*)(row + 4);
        ULL a0 = n01.x, a1 = n01.y, a2 = n23.x, a3 = n23.y;
        float2 wv = *(const float2*)&wtb[k * 64 + lane * 2];
        ULL w0 = pk2(wv.x, wv.x), w1 = pk2(wv.y, wv.y);
        fma2(c2[0][0], w0, a0); fma2(c2[0][1], w0, a1); fma2(c2[0][2], w0, a2); fma2(c2[0][3], w0, a3);
        fma2(c2[1][0], w1, a0); fma2(c2[1][1], w1, a1); fma2(c2[1][2], w1, a2); fma2(c2[1][3], w1, a3);
    }
    float b0 = bb[lane * 2], b1 = bb[lane * 2 + 1];
    float s0 = 0.f, q0 = 0.f, s1 = 0.f, q1 = 0.f;
#pragma unroll
    for (int p = 0; p < 4; p++) {
        float x0, x1, y0, y1;
        upk(c2[0][p], x0, x1);
        upk(c2[1][p], y0, y1);
        int na = n0 + nb + 2 * p;
        if (na < N) {
            float o0 = x0 + b0, o1 = y0 + b1;
            *(float2*)&out[na * 64 + lane * 2] = make_float2(o0, o1);
            s0 += o0; q0 = fmaf(o0, o0, q0); s1 += o1; q1 = fmaf(o1, o1, q1);
        }
        if (na + 1 < N) {
            float o0 = x1 + b0, o1 = y1 + b1;
            *(float2*)&out[(na + 1) * 64 + lane * 2] = make_float2(o0, o1);
            s0 += o0; q0 = fmaf(o0, o0, q0); s1 += o1; q1 = fmaf(o1, o1, q1);
        }
    }
    RS[wrp * 64 + lane * 2] = s0; RS[wrp * 64 + lane * 2 + 1] = s1;
    RQ[wrp * 64 + lane * 2] = q0; RQ[wrp * 64 + lane * 2 + 1] = q1;
    __syncthreads();
    if (tid < 128) {
        int c = tid & 63;
        const float* P = (tid >= 64) ? RQ : RS;
        float v = 0.f;
#pragma unroll
        for (int w = 0; w < 8; w++) v += P[w * 64 + c];
        atomicAdd(&g_stats[bnidx * 128 + ((tid >= 64) ? 64 : 0) + c], v);
    }
}

// ---------------- fc1 head GEMM (64-node tiles, R13 form) -----------------
__global__ void __launch_bounds__(256) fc1_kernel(
    const float* __restrict__ pre1, const float* __restrict__ pre2, const float* __restrict__ pre3,
    const float* __restrict__ bn0w, const float* __restrict__ bn0b,
    const float* __restrict__ bn1w, const float* __restrict__ bn1b,
    const float* __restrict__ bn2w, const float* __restrict__ bn2b,
    const float* __restrict__ fb,
    float* __restrict__ out, int N)
{
    extern __shared__ float smem[];
    float* A_s = smem;                      // 192*ASTRIDE
    float* RS  = A_s + 192 * ASTRIDE;       // 512
    float* RQ  = RS + 512;                  // 512
    float* sc  = RQ + 512;                  // 192
    float* sh  = sc + 192;                  // 192
    int*   s_comb = (int*)(sh + 192);       // 64

    const int tid = threadIdx.x;
    const int n0 = blockIdx.x * 64;
    if (tid < 192) {
        int l = tid >> 6, c = tid & 63;
        const float* w = (l == 0) ? bn0w : ((l == 1) ? bn1w : bn2w);
        const float* b = (l == 0) ? bn0b : ((l == 1) ? bn1b : bn2b);
        float m   = g_stats[l * 128 + c] / (float)N;
        float var = g_stats[l * 128 + 64 + c] / (float)N - m * m;
        float inv = rsqrtf(var + 1e-5f);
        float a   = w[c] * inv;
        sc[tid] = a;
        sh[tid] = b[c] - m * a;
    }
    if (tid >= 192 && tid < 256) {
        int nl = tid - 192;
        int n = n0 + nl;
        s_comb[nl] = (n < N) ? (g_comb[n] >> 1) : 0;   // U rows are 64 wide
    }
    __syncthreads();

    for (int i = tid; i < 64 * 192; i += 256) {
        int nl = i / 192, k = i - nl * 192;
        int n = n0 + nl;
        float v = 0.f;
        if (n < N) {
            int l = k >> 6, c = k & 63;
            const float* pr = (l == 0) ? pre1 : ((l == 1) ? pre2 : pre3);
            float p = fmaf(pr[n * 64 + c], sc[k], sh[k]);
            v = fmaxf(p, 0.01f * p);
        }
        A_s[k * ASTRIDE + nl] = v;
    }
    __syncthreads();

    const int lane = tid & 31, wrp = tid >> 5;
    const int nb = wrp * 8;

    ULL c2[2][4];
#pragma unroll
    for (int i = 0; i < 2; i++)
#pragma unroll
        for (int p = 0; p < 4; p++) c2[i][p] = 0ULL;

#pragma unroll 8
    for (int k = 0; k < 192; k++) {
        const float* row = &A_s[k * ASTRIDE + nb];
        ulonglong2 n01 = *(const ulonglong2*)(row);
        ulonglong2 n23 = *(const ulonglong2*)(row + 4);
        ULL a0 = n01.x, a1 = n01.y, a2 = n23.x, a3 = n23.y;
        float2 wv = *(const float2*)&g_fc1t[(128 + k) * 64 + lane * 2];
        ULL w0 = pk2(wv.x, wv.x), w1 = pk2(wv.y, wv.y);
        fma2(c2[0][0], w0, a0); fma2(c2[0][1], w0, a1); fma2(c2[0][2], w0, a2); fma2(c2[0][3], w0, a3);
        fma2(c2[1][0], w1, a0); fma2(c2[1][1], w1, a1); fma2(c2[1][2], w1, a2); fma2(c2[1][3], w1, a3);
    }

    float b0 = fb[lane * 2], b1 = fb[lane * 2 + 1];
    float s0 = 0.f, q0 = 0.f, s1 = 0.f, q1 = 0.f;
#pragma unroll
    for (int p = 0; p < 4; p++) {
        float x0, x1, y0, y1;
        upk(c2[0][p], x0, x1);
        upk(c2[1][p], y0, y1);
        int na = n0 + nb + 2 * p;
        if (na < N) {
            float2 uv = *(const float2*)&g_U[s_comb[nb + 2 * p] + lane * 2];
            float o0 = x0 + b0 + uv.x, o1 = y0 + b1 + uv.y;
            *(float2*)&out[na * 64 + lane * 2] = make_float2(o0, o1);
            s0 += o0; q0 = fmaf(o0, o0, q0); s1 += o1; q1 = fmaf(o1, o1, q1);
        }
        if (na + 1 < N) {
            float2 uv = *(const float2*)&g_U[s_comb[nb + 2 * p + 1] + lane * 2];
            float o0 = x1 + b0 + uv.x, o1 = y1 + b1 + uv.y;
            *(float2*)&out[(na + 1) * 64 + lane * 2] = make_float2(o0, o1);
            s0 += o0; q0 = fmaf(o0, o0, q0); s1 += o1; q1 = fmaf(o1, o1, q1);
        }
    }
    RS[wrp * 64 + lane * 2] = s0; RS[wrp * 64 + lane * 2 + 1] = s1;
    RQ[wrp * 64 + lane * 2] = q0; RQ[wrp * 64 + lane * 2 + 1] = q1;
    __syncthreads();
    if (tid < 128) {
        int c = tid & 63;
        const float* P = (tid >= 64) ? RQ : RS;
        float v = 0.f;
#pragma unroll
        for (int w = 0; w < 8; w++) v += P[w * 64 + c];
        atomicAdd(&g_stats[3 * 128 + ((tid >= 64) ? 64 : 0) + c], v);
    }
}

// ---------------- final head ----------------
__global__ void final_kernel(const float* __restrict__ hpre,
                             const float* __restrict__ bnw, const float* __restrict__ bnb,
                             const float* __restrict__ fc2w, const float* __restrict__ fc2b,
                             float* __restrict__ out, int N) {
    __shared__ float sc[64], sh[64], w2s[64];
    if (threadIdx.x < 64) {
        int c = threadIdx.x;
        float m   = g_stats[3 * 128 + c] / (float)N;
        float var = g_stats[3 * 128 + 64 + c] / (float)N - m * m;
        float inv = rsqrtf(var + 1e-5f);
        float a   = bnw[c] * inv;
        sc[c]  = a;
        sh[c]  = bnb[c] - m * a;
        w2s[c] = fc2w[c];
    }
    __syncthreads();
    int wid  = (blockIdx.x * blockDim.x + threadIdx.x) >> 5;
    int lane = threadIdx.x & 31;
    if (wid >= N) return;
    float2 v = *(const float2*)&hpre[wid * 64 + lane * 2];
    float x = fmaf(v.x, sc[lane * 2], sh[lane * 2]);         x = fmaxf(x, 0.01f * x);
    float y = fmaf(v.y, sc[lane * 2 + 1], sh[lane * 2 + 1]); y = fmaxf(y, 0.01f * y);
    float acc = fmaf(x, w2s[lane * 2], y * w2s[lane * 2 + 1]);
#pragma unroll
    for (int off = 16; off; off >>= 1) acc += __shfl_xor_sync(0xffffffffu, acc, off);
    if (lane == 0) out[wid] = 1.f / (1.f + expf(-(acc + fc2b[0])));
}

// ---------------- launch ----------------
extern "C" void kernel_launch(void* const* d_in, const int* in_sizes, int n_in,
                              void* d_out, int out_size) {
    const float* emb_deg = (const float*)d_in[0];
    const float* emb_lab = (const float*)d_in[1];
    const float* w0a = (const float*)d_in[2];  const float* b0a = (const float*)d_in[3];
    const float* w0b = (const float*)d_in[4];  const float* b0b = (const float*)d_in[5];
    const float* bn0w = (const float*)d_in[6]; const float* bn0b = (const float*)d_in[7];
    const float* w1a = (const float*)d_in[8];  const float* b1a = (const float*)d_in[9];
    const float* w1b = (const float*)d_in[10]; const float* b1b = (const float*)d_in[11];
    const float* bn1w = (const float*)d_in[12]; const float* bn1b = (const float*)d_in[13];
    const float* w2a = (const float*)d_in[14]; const float* b2a = (const float*)d_in[15];
    const float* w2b = (const float*)d_in[16]; const float* b2b = (const float*)d_in[17];
    const float* bn2w = (const float*)d_in[18]; const float* bn2b = (const float*)d_in[19];
    const float* fc1w = (const float*)d_in[20]; const float* fc1b = (const float*)d_in[21];
    const float* fcbnw = (const float*)d_in[22]; const float* fcbnb = (const float*)d_in[23];
    const float* fc2w = (const float*)d_in[24]; const float* fc2b = (const float*)d_in[25];
    const int* node_deg = (const int*)d_in[26];
    const int* node_lab = (const int*)d_in[27];
    const int* edge = (const int*)d_in[28];

    const int N = in_sizes[26];
    const int E = in_sizes[28] / 2;
    const int* src  = edge;
    const int* dstp = edge + E;
    float* out = (float*)d_out;

    float *hin, *pre1, *pre2, *pre3, *pre4;
    float *wt0b, *wt1a, *wt1b, *wt2a, *wt2b;
    cudaGetSymbolAddress((void**)&hin,  g_hin);
    cudaGetSymbolAddress((void**)&pre1, g_pre1);
    cudaGetSymbolAddress((void**)&pre2, g_pre2);
    cudaGetSymbolAddress((void**)&pre3, g_pre3);
    cudaGetSymbolAddress((void**)&pre4, g_pre4);
    cudaGetSymbolAddress((void**)&wt0b, g_wt0b);
    cudaGetSymbolAddress((void**)&wt1a, g_wt1a);
    cudaGetSymbolAddress((void**)&wt1b, g_wt1b);
    cudaGetSymbolAddress((void**)&wt2a, g_wt2a);
    cudaGetSymbolAddress((void**)&wt2b, g_wt2b);

    const int TB = 256;
    const int mlpBlocks  = (N + 63) / 64;
    const int warpBlocks = (N * 32 + TB - 1) / TB;
    const int hwBlocks   = (N * 16 + TB - 1) / TB;
    const int scanBlocks = (N + 255) / 256;
    const int prepBlocks = (45056 + 255) / 256;

    const int SM_TBL   = (128 * ASTRIDE + 32 * 132) * 4;             // 51712
    const int SM_MLP0B = (128 * ASTRIDE + 1024) * 4;                 // 38912
    const int SM_MLP1  = (64 * ASTRIDE + 1024) * 4;                  // 21504
    const int SM_FC1   = (192 * ASTRIDE + 1024 + 384 + 64) * 4;      // 58112
    cudaFuncSetAttribute(tables_kernel, cudaFuncAttributeMaxDynamicSharedMemorySize, SM_TBL);
    cudaFuncSetAttribute(mlp0b_kernel,  cudaFuncAttributeMaxDynamicSharedMemorySize, SM_MLP0B);
    cudaFuncSetAttribute(mlp_kernel,    cudaFuncAttributeMaxDynamicSharedMemorySize, SM_MLP1);
    cudaFuncSetAttribute(fc1_kernel,    cudaFuncAttributeMaxDynamicSharedMemorySize, SM_FC1);

    static cudaStream_t sPrep = []() {
        cudaStream_t s; cudaStreamCreateWithFlags(&s, cudaStreamNonBlocking); return s;
    }();
    static cudaEvent_t evFork = []() {
        cudaEvent_t e; cudaEventCreateWithFlags(&e, cudaEventDisableTiming); return e;
    }();
    static cudaEvent_t evJoin = []() {
        cudaEvent_t e; cudaEventCreateWithFlags(&e, cudaEventDisableTiming); return e;
    }();

    // fork: prep branch on side stream
    cudaEventRecord(evFork, 0);
    cudaStreamWaitEvent(sPrep, evFork, 0);
    prep_kernel<<<prepBlocks, 256, 0, sPrep>>>(w0b, w1a, w1b, w2a, w2b, fc1w);
    tables_kernel<<<32, 256, SM_TBL, sPrep>>>(w0a, fc1w, emb_deg, emb_lab);
    cudaEventRecord(evJoin, sPrep);

    // CSR branch on main stream
    hist_kernel<<<(E + TB - 1) / TB, TB>>>(dstp, node_deg, node_lab, E, N);
    scan_kernel<<<scanBlocks, 256>>>(N);
    scatter_kernel<<<(E + TB - 1) / TB, TB>>>(src, dstp, E, N);

    // join
    cudaStreamWaitEvent(0, evJoin, 0);

    // layer 0
    agg0t_kernel<<<warpBlocks, TB>>>(hin, N);
    mlp0b_kernel<<<mlpBlocks, 256, SM_MLP0B>>>(hin, b0a, wt0b, b0b, pre1, N);

    // layer 1
    aggbn_kernel<<<hwBlocks, TB>>>(pre1, bn0w, bn0b, hin, N, 0);
    mlp_kernel<<<mlpBlocks, 256, SM_MLP1>>>(hin, wt1a, b1a, wt1b, b1b, pre2, N, 1);

    // layer 2
    aggbn_kernel<<<hwBlocks, TB>>>(pre2, bn1w, bn1b, hin, N, 1);
    mlp_kernel<<<mlpBlocks, 256, SM_MLP1>>>(hin, wt2a, b2a, wt2b, b2b, pre3, N, 2);

    // head
    fc1_kernel<<<mlpBlocks, 256, SM_FC1>>>(pre1, pre2, pre3,
                                           bn0w, bn0b, bn1w, bn1b, bn2w, bn2b,
                                           fc1b, pre4, N);
    final_kernel<<<warpBlocks, TB>>>(pre4, fcbnw, fcbnb, fc2w, fc2b, out, N);
}

// round 16
// speedup vs baseline: 1.1615x; 1.0730x over previous
#include <cuda_runtime.h>
#include <cuda_fp16.h>
#include <math.h>

#define NN 50000
#define NE 800000
typedef unsigned long long ULL;

// ---------------- device scratch ----------------
__device__ float  g_hin [NN * 128];
__device__ __half g_pre1[NN * 64];
__device__ __half g_pre2[NN * 64];
__device__ __half g_pre3[NN * 64];
__device__ float  g_pre4[NN * 64];
__device__ float  g_wt0b[128 * 64];
__device__ float  g_wt1a[64 * 64];
__device__ float  g_wt1b[64 * 64];
__device__ float  g_wt2a[64 * 64];
__device__ float  g_wt2b[64 * 64];
__device__ float  g_fc1t[320 * 64];
__device__ float  g_U[1024 * 64];     // U[c][m] = x0_c @ fc1_w[:, :128]^T  (fp32)
__device__ __half g_T[1024 * 128];    // T[c][m] = x0_c @ w0a^T             (fp16)
__device__ int    g_comb[NN];         // (deg*16+lab)*128
__device__ int    g_cnt[NN];
__device__ int    g_rowptr[NN + 1];
__device__ int    g_cursor[NN];
__device__ ULL    g_edge[NE];         // lo32 = src*64, hi32 = comb
__device__ unsigned int g_part[256];
__device__ float  g_stats[4 * 128];

#define ASTRIDE 68   // floats per smem row: 16B-aligned -> LDS.128

// ---------------- f32x2 / fp16 helpers ----------------
__device__ __forceinline__ ULL pk2(float x, float y) {
    ULL r; asm("mov.b64 %0, {%1,%2};" : "=l"(r) : "f"(x), "f"(y)); return r;
}
__device__ __forceinline__ void upk(ULL v, float& x, float& y) {
    asm("mov.b64 {%0,%1}, %2;" : "=f"(x), "=f"(y) : "l"(v));
}
__device__ __forceinline__ void fma2(ULL& d, ULL a, ULL b) {
    asm("fma.rn.f32x2 %0, %1, %2, %0;" : "+l"(d) : "l"(a), "l"(b));
}
// load 4 consecutive halves -> float4 (one LDG.64)
__device__ __forceinline__ float4 ldh4(const __half* p) {
    uint2 u = *(const uint2*)p;
    float2 f0 = __half22float2(*(__half2*)&u.x);
    float2 f1 = __half22float2(*(__half2*)&u.y);
    return make_float4(f0.x, f0.y, f1.x, f1.y);
}
__device__ __forceinline__ void sth2(__half* p, float x, float y) {
    *(__half2*)p = __floats2half2_rn(x, y);
}

// ---------------- CSR A1: histogram by dst + comb ----------
__global__ void hist_kernel(const int* __restrict__ dst,
                            const int* __restrict__ ndeg, const int* __restrict__ nlab,
                            int E, int N) {
    int i = blockIdx.x * blockDim.x + threadIdx.x;
    if (i < E) atomicAdd(&g_cnt[dst[i]], 1);
    if (i < N) g_comb[i] = (ndeg[i] * 16 + nlab[i]) << 7;
}

// ---------------- CSR A2: decoupled-lookback scan ----------
__global__ void scan_kernel(int N) {
    __shared__ int sm[256];
    __shared__ int s_base;
    const int b = blockIdx.x;
    const int t = threadIdx.x;
    int idx = b * 256 + t;
    int v = (idx < N) ? g_cnt[idx] : 0;
    sm[t] = v;
    __syncthreads();
    for (int o = 1; o < 256; o <<= 1) {
        int u = (t >= o) ? sm[t - o] : 0;
        __syncthreads(); sm[t] += u; __syncthreads();
    }
    if (t == 255) {
        int total = sm[255];
        if (b == 0) {
            atomicExch(&g_part[0], 0x80000000u | (unsigned)total);
            s_base = 0;
        } else {
            atomicExch(&g_part[b], 0x40000000u | (unsigned)total);
            int excl = 0;
            for (int p = b - 1;;) {
                unsigned pv;
                do { pv = atomicAdd(&g_part[p], 0u); } while (pv < 0x40000000u);
                excl += (int)(pv & 0x3FFFFFFFu);
                if (pv >= 0x80000000u) break;
                p--;
            }
            atomicExch(&g_part[b], 0x80000000u | (unsigned)(excl + total));
            s_base = excl;
        }
    }
    __syncthreads();
    int excl_local = sm[t] - v + s_base;
    if (idx < N) {
        g_rowptr[idx] = excl_local;
        g_cursor[idx] = excl_local;
        if (idx == N - 1) g_rowptr[N] = excl_local + v;
    }
}

// ---------------- CSR A3: scatter packed edge record -------
__global__ void scatter_kernel(const int* __restrict__ src, const int* __restrict__ dst, int E, int N) {
    int i = blockIdx.x * blockDim.x + threadIdx.x;
    if (i < E) {
        int s = src[i];
        int p = atomicAdd(&g_cursor[dst[i]], 1);
        g_edge[p] = ((ULL)(unsigned)g_comb[s] << 32) | (unsigned)(s * 64);
    }
    if (i < N) g_cnt[i] = 0;
    if (i < 512) g_stats[i] = 0.f;
    if (i < 256) g_part[i] = 0u;
}

// ---------------- prep B1: small weight transposes ---------
__global__ void prep_kernel(const float* __restrict__ w0b,
                            const float* __restrict__ w1a, const float* __restrict__ w1b,
                            const float* __restrict__ w2a, const float* __restrict__ w2b,
                            const float* __restrict__ fc1w) {
    int j = blockIdx.x * 256 + threadIdx.x;
    if (j < 8192)  { int m = j >> 7, k = j & 127; g_wt0b[k * 64 + m] = w0b[j]; return; }
    if ((j -= 8192) < 4096)  { int m = j >> 6, k = j & 63; g_wt1a[k * 64 + m] = w1a[j]; return; }
    if ((j -= 4096) < 4096)  { int m = j >> 6, k = j & 63; g_wt1b[k * 64 + m] = w1b[j]; return; }
    if ((j -= 4096) < 4096)  { int m = j >> 6, k = j & 63; g_wt2a[k * 64 + m] = w2a[j]; return; }
    if ((j -= 4096) < 4096)  { int m = j >> 6, k = j & 63; g_wt2b[k * 64 + m] = w2b[j]; return; }
    if ((j -= 4096) < 20480) { int m = j / 320, k = j - m * 320; g_fc1t[k * 64 + m] = fc1w[j]; return; }
}

// ---------------- prep B2: T (fp16) and U (fp32) tables -----
__global__ void __launch_bounds__(256) tables_kernel(
    const float* __restrict__ w0a, const float* __restrict__ fc1w,
    const float* __restrict__ ed, const float* __restrict__ el)
{
    extern __shared__ float smem[];
    float* A_s = smem;                   // 128*ASTRIDE
    float* W_s = smem + 128 * ASTRIDE;   // 32*132

    const int tid  = threadIdx.x;
    const bool isT = blockIdx.x < 16;
    const int c0   = (blockIdx.x & 15) * 64;
    const int M    = isT ? 128 : 64;
    const int ldW  = isT ? 128 : 320;
    const float* W = isT ? w0a : fc1w;

    for (int i = tid; i < 64 * 32; i += 256) {
        int cl = i >> 5, k4 = i & 31;
        int c = c0 + cl;
        const float* tbl = (k4 < 16) ? (ed + (c >> 4) * 64) : (el + (c & 15) * 64 - 64);
        float4 v = *(const float4*)&tbl[k4 * 4];
        A_s[(4 * k4 + 0) * ASTRIDE + cl] = v.x;
        A_s[(4 * k4 + 1) * ASTRIDE + cl] = v.y;
        A_s[(4 * k4 + 2) * ASTRIDE + cl] = v.z;
        A_s[(4 * k4 + 3) * ASTRIDE + cl] = v.w;
    }

    const int lane = tid & 31, wrp = tid >> 5;
    const int nb = wrp * 8;

    ULL acc[4][4];
#pragma unroll
    for (int i = 0; i < 4; i++)
#pragma unroll
        for (int p = 0; p < 4; p++) acc[i][p] = 0ULL;

    for (int kc = 0; kc < 4; kc++) {
        __syncthreads();
        for (int i = tid; i < 32 * M; i += 256) {
            int m = i >> 5, kk = i & 31;
            W_s[kk * 132 + m] = W[m * ldW + kc * 32 + kk];
        }
        __syncthreads();
#pragma unroll 8
        for (int kk = 0; kk < 32; kk++) {
            int k = kc * 32 + kk;
            const float* row = &A_s[k * ASTRIDE + nb];
            ulonglong2 n01 = *(const ulonglong2*)(row);
            ulonglong2 n23 = *(const ulonglong2*)(row + 4);
            ULL a0 = n01.x, a1 = n01.y, a2 = n23.x, a3 = n23.y;
            if (isT) {
                float4 w4 = *(const float4*)&W_s[kk * 132 + lane * 4];
                ULL w0 = pk2(w4.x, w4.x), w1 = pk2(w4.y, w4.y);
                ULL w2 = pk2(w4.z, w4.z), w3 = pk2(w4.w, w4.w);
                fma2(acc[0][0], w0, a0); fma2(acc[0][1], w0, a1); fma2(acc[0][2], w0, a2); fma2(acc[0][3], w0, a3);
                fma2(acc[1][0], w1, a0); fma2(acc[1][1], w1, a1); fma2(acc[1][2], w1, a2); fma2(acc[1][3], w1, a3);
                fma2(acc[2][0], w2, a0); fma2(acc[2][1], w2, a1); fma2(acc[2][2], w2, a2); fma2(acc[2][3], w2, a3);
                fma2(acc[3][0], w3, a0); fma2(acc[3][1], w3, a1); fma2(acc[3][2], w3, a2); fma2(acc[3][3], w3, a3);
            } else {
                float2 wv = *(const float2*)&W_s[kk * 132 + lane * 2];
                ULL w0 = pk2(wv.x, wv.x), w1 = pk2(wv.y, wv.y);
                fma2(acc[0][0], w0, a0); fma2(acc[0][1], w0, a1); fma2(acc[0][2], w0, a2); fma2(acc[0][3], w0, a3);
                fma2(acc[1][0], w1, a0); fma2(acc[1][1], w1, a1); fma2(acc[1][2], w1, a2); fma2(acc[1][3], w1, a3);
            }
        }
    }

#pragma unroll
    for (int p = 0; p < 4; p++) {
        int c = c0 + nb + 2 * p;
        if (isT) {
            float a0x, a0y, a1x, a1y, a2x, a2y, a3x, a3y;
            upk(acc[0][p], a0x, a0y); upk(acc[1][p], a1x, a1y);
            upk(acc[2][p], a2x, a2y); upk(acc[3][p], a3x, a3y);
            uint2 u0, u1;
            *(__half2*)&u0.x = __floats2half2_rn(a0x, a1x);
            *(__half2*)&u0.y = __floats2half2_rn(a2x, a3x);
            *(__half2*)&u1.x = __floats2half2_rn(a0y, a1y);
            *(__half2*)&u1.y = __floats2half2_rn(a2y, a3y);
            *(uint2*)&g_T[c * 128 + lane * 4]       = u0;
            *(uint2*)&g_T[(c + 1) * 128 + lane * 4] = u1;
        } else {
            float x0, x1, y0, y1;
            upk(acc[0][p], x0, x1); upk(acc[1][p], y0, y1);
            *(float2*)&g_U[c * 64 + lane * 2]       = make_float2(x0, y0);
            *(float2*)&g_U[(c + 1) * 64 + lane * 2] = make_float2(x1, y1);
        }
    }
}

// ---------------- layer-0 agg from fp16 T table (warp per node) -----------
__global__ void agg0t_kernel(float* __restrict__ hout, int N) {
    int wid  = (blockIdx.x * blockDim.x + threadIdx.x) >> 5;
    int lane = threadIdx.x & 31;
    if (wid >= N) return;
    const int offi = lane * 4;
    float4 acc = ldh4(&g_T[g_comb[wid] + offi]);
    int beg = g_rowptr[wid], end = g_rowptr[wid + 1];
    int e = beg;
    for (; e + 8 <= end; e += 8) {
        ULL e0 = g_edge[e],     e1 = g_edge[e + 1], e2 = g_edge[e + 2], e3 = g_edge[e + 3];
        ULL e4 = g_edge[e + 4], e5 = g_edge[e + 5], e6 = g_edge[e + 6], e7 = g_edge[e + 7];
        float4 v0 = ldh4(&g_T[(int)(e0 >> 32) + offi]);
        float4 v1 = ldh4(&g_T[(int)(e1 >> 32) + offi]);
        float4 v2 = ldh4(&g_T[(int)(e2 >> 32) + offi]);
        float4 v3 = ldh4(&g_T[(int)(e3 >> 32) + offi]);
        float4 v4 = ldh4(&g_T[(int)(e4 >> 32) + offi]);
        float4 v5 = ldh4(&g_T[(int)(e5 >> 32) + offi]);
        float4 v6 = ldh4(&g_T[(int)(e6 >> 32) + offi]);
        float4 v7 = ldh4(&g_T[(int)(e7 >> 32) + offi]);
        acc.x += ((v0.x + v1.x) + (v2.x + v3.x)) + ((v4.x + v5.x) + (v6.x + v7.x));
        acc.y += ((v0.y + v1.y) + (v2.y + v3.y)) + ((v4.y + v5.y) + (v6.y + v7.y));
        acc.z += ((v0.z + v1.z) + (v2.z + v3.z)) + ((v4.z + v5.z) + (v6.z + v7.z));
        acc.w += ((v0.w + v1.w) + (v2.w + v3.w)) + ((v4.w + v5.w) + (v6.w + v7.w));
    }
    for (; e < end; e++) {
        float4 v = ldh4(&g_T[(int)(g_edge[e] >> 32) + offi]);
        acc.x += v.x; acc.y += v.y; acc.z += v.z; acc.w += v.w;
    }
    *(float4*)&hout[wid * 128 + offi] = acc;
}

// ---------------- layer-0 second GEMM (fp16 pre out) ----------------------
__global__ void __launch_bounds__(256) mlp0b_kernel(
    const float* __restrict__ hin, const float* __restrict__ ba,
    const float* __restrict__ wtb, const float* __restrict__ bb,
    __half* __restrict__ out, int N)
{
    extern __shared__ float smem[];
    float* A_s = smem;                    // 128*ASTRIDE
    float* RS  = smem + 128 * ASTRIDE;    // 512
    float* RQ  = RS + 512;                // 512

    const int tid = threadIdx.x;
    const int n0  = blockIdx.x * 64;

    for (int i = tid; i < 64 * 32; i += 256) {
        int nl = i >> 5, k4 = i & 31;
        int n = n0 + nl;
        float4 v = make_float4(0.f, 0.f, 0.f, 0.f);
        if (n < N) {
            v = *(const float4*)&hin[n * 128 + k4 * 4];
            float4 bv = *(const float4*)&ba[k4 * 4];
            v.x += bv.x; v.x = fmaxf(v.x, 0.01f * v.x);
            v.y += bv.y; v.y = fmaxf(v.y, 0.01f * v.y);
            v.z += bv.z; v.z = fmaxf(v.z, 0.01f * v.z);
            v.w += bv.w; v.w = fmaxf(v.w, 0.01f * v.w);
        }
        A_s[(4 * k4 + 0) * ASTRIDE + nl] = v.x;
        A_s[(4 * k4 + 1) * ASTRIDE + nl] = v.y;
        A_s[(4 * k4 + 2) * ASTRIDE + nl] = v.z;
        A_s[(4 * k4 + 3) * ASTRIDE + nl] = v.w;
    }
    __syncthreads();

    const int lane = tid & 31, wrp = tid >> 5;
    const int nb = wrp * 8;

    ULL c2[2][4];
#pragma unroll
    for (int i = 0; i < 2; i++)
#pragma unroll
        for (int p = 0; p < 4; p++) c2[i][p] = 0ULL;
#pragma unroll 8
    for (int k = 0; k < 128; k++) {
        const float* row = &A_s[k * ASTRIDE + nb];
        ulonglong2 n01 = *(const ulonglong2*)(row);
        ulonglong2 n23 = *(const ulonglong2*)(row + 4);
        ULL a0 = n01.x, a1 = n01.y, a2 = n23.x, a3 = n23.y;
        float2 wv = *(const float2*)&wtb[k * 64 + lane * 2];
        ULL w0 = pk2(wv.x, wv.x), w1 = pk2(wv.y, wv.y);
        fma2(c2[0][0], w0, a0); fma2(c2[0][1], w0, a1); fma2(c2[0][2], w0, a2); fma2(c2[0][3], w0, a3);
        fma2(c2[1][0], w1, a0); fma2(c2[1][1], w1, a1); fma2(c2[1][2], w1, a2); fma2(c2[1][3], w1, a3);
    }
    float b0 = bb[lane * 2], b1 = bb[lane * 2 + 1];
    float s0 = 0.f, q0 = 0.f, s1 = 0.f, q1 = 0.f;
#pragma unroll
    for (int p = 0; p < 4; p++) {
        float x0, x1, y0, y1;
        upk(c2[0][p], x0, x1);
        upk(c2[1][p], y0, y1);
        int na = n0 + nb + 2 * p;
        if (na < N) {
            float o0 = x0 + b0, o1 = y0 + b1;
            sth2(&out[na * 64 + lane * 2], o0, o1);
            s0 += o0; q0 = fmaf(o0, o0, q0); s1 += o1; q1 = fmaf(o1, o1, q1);
        }
        if (na + 1 < N) {
            float o0 = x1 + b0, o1 = y1 + b1;
            sth2(&out[(na + 1) * 64 + lane * 2], o0, o1);
            s0 += o0; q0 = fmaf(o0, o0, q0); s1 += o1; q1 = fmaf(o1, o1, q1);
        }
    }
    RS[wrp * 64 + lane * 2] = s0; RS[wrp * 64 + lane * 2 + 1] = s1;
    RQ[wrp * 64 + lane * 2] = q0; RQ[wrp * 64 + lane * 2 + 1] = q1;
    __syncthreads();
    if (tid < 128) {
        int c = tid & 63;
        const float* P = (tid >= 64) ? RQ : RS;
        float v = 0.f;
#pragma unroll
        for (int w = 0; w < 8; w++) v += P[w * 64 + c];
        atomicAdd(&g_stats[((tid >= 64) ? 64 : 0) + c], v);
    }
}

// ---------------- aggregation fused BN+lrelu (half-warp, fp16 gathers) ----
__global__ void aggbn_kernel(const __half* __restrict__ pre,
                             const float* __restrict__ bnw, const float* __restrict__ bnb,
                             float* __restrict__ hout, int N, int bnidx) {
    __shared__ float sc[64], sh[64];
    if (threadIdx.x < 64) {
        int c = threadIdx.x;
        float m   = g_stats[bnidx * 128 + c] / (float)N;
        float var = g_stats[bnidx * 128 + 64 + c] / (float)N - m * m;
        float inv = rsqrtf(var + 1e-5f);
        float a   = bnw[c] * inv;
        sc[c] = a;
        sh[c] = bnb[c] - m * a;
    }
    __syncthreads();
    int hw  = (blockIdx.x * blockDim.x + threadIdx.x) >> 4;   // half-warp = node
    int l16 = threadIdx.x & 15;
    if (hw >= N) return;
    const int li = l16 * 4;
    float4 a4 = *(const float4*)&sc[li];
    float4 c4 = *(const float4*)&sh[li];
#define BNR4(v) { v.x = fmaf(v.x, a4.x, c4.x); v.x = fmaxf(v.x, 0.01f * v.x); \
                  v.y = fmaf(v.y, a4.y, c4.y); v.y = fmaxf(v.y, 0.01f * v.y); \
                  v.z = fmaf(v.z, a4.z, c4.z); v.z = fmaxf(v.z, 0.01f * v.z); \
                  v.w = fmaf(v.w, a4.w, c4.w); v.w = fmaxf(v.w, 0.01f * v.w); }
    float4 acc = ldh4(&pre[hw * 64 + li]);
    BNR4(acc);
    int beg = g_rowptr[hw], end = g_rowptr[hw + 1];
    int e = beg;
    for (; e + 8 <= end; e += 8) {
        ULL e0 = g_edge[e],     e1 = g_edge[e + 1], e2 = g_edge[e + 2], e3 = g_edge[e + 3];
        ULL e4 = g_edge[e + 4], e5 = g_edge[e + 5], e6 = g_edge[e + 6], e7 = g_edge[e + 7];
        float4 v0 = ldh4(&pre[(int)(unsigned)e0 + li]);
        float4 v1 = ldh4(&pre[(int)(unsigned)e1 + li]);
        float4 v2 = ldh4(&pre[(int)(unsigned)e2 + li]);
        float4 v3 = ldh4(&pre[(int)(unsigned)e3 + li]);
        float4 v4 = ldh4(&pre[(int)(unsigned)e4 + li]);
        float4 v5 = ldh4(&pre[(int)(unsigned)e5 + li]);
        float4 v6 = ldh4(&pre[(int)(unsigned)e6 + li]);
        float4 v7 = ldh4(&pre[(int)(unsigned)e7 + li]);
        BNR4(v0); BNR4(v1); BNR4(v2); BNR4(v3); BNR4(v4); BNR4(v5); BNR4(v6); BNR4(v7);
        acc.x += ((v0.x + v1.x) + (v2.x + v3.x)) + ((v4.x + v5.x) + (v6.x + v7.x));
        acc.y += ((v0.y + v1.y) + (v2.y + v3.y)) + ((v4.y + v5.y) + (v6.y + v7.y));
        acc.z += ((v0.z + v1.z) + (v2.z + v3.z)) + ((v4.z + v5.z) + (v6.z + v7.z));
        acc.w += ((v0.w + v1.w) + (v2.w + v3.w)) + ((v4.w + v5.w) + (v6.w + v7.w));
    }
    for (; e < end; e++) {
        float4 v = ldh4(&pre[(int)(unsigned)g_edge[e] + li]);
        BNR4(v);
        acc.x += v.x; acc.y += v.y; acc.z += v.z; acc.w += v.w;
    }
#undef BNR4
    *(float4*)&hout[hw * 64 + li] = acc;
}

// ---------------- GIN MLP layers 1/2 (fp16 pre out) -----------------------
__global__ void __launch_bounds__(256) mlp_kernel(
    const float* __restrict__ hin,
    const float* __restrict__ wta, const float* __restrict__ ba,
    const float* __restrict__ wtb, const float* __restrict__ bb,
    __half* __restrict__ out, int N, int bnidx)
{
    extern __shared__ float smem[];
    float* A_s = smem;                   // 64*ASTRIDE (reused for H)
    float* RS  = smem + 64 * ASTRIDE;    // 512
    float* RQ  = RS + 512;               // 512

    const int tid = threadIdx.x;
    const int n0  = blockIdx.x * 64;

    for (int i = tid; i < 64 * 16; i += 256) {
        int nl = i >> 4, k4 = i & 15;
        int n = n0 + nl;
        float4 v = make_float4(0.f, 0.f, 0.f, 0.f);
        if (n < N) v = *(const float4*)&hin[n * 64 + k4 * 4];
        A_s[(4 * k4 + 0) * ASTRIDE + nl] = v.x;
        A_s[(4 * k4 + 1) * ASTRIDE + nl] = v.y;
        A_s[(4 * k4 + 2) * ASTRIDE + nl] = v.z;
        A_s[(4 * k4 + 3) * ASTRIDE + nl] = v.w;
    }
    __syncthreads();

    const int lane = tid & 31, wrp = tid >> 5;
    const int nb = wrp * 8;

    ULL acc[2][4];
#pragma unroll
    for (int i = 0; i < 2; i++)
#pragma unroll
        for (int p = 0; p < 4; p++) acc[i][p] = 0ULL;
#pragma unroll 8
    for (int k = 0; k < 64; k++) {
        const float* row = &A_s[k * ASTRIDE + nb];
        ulonglong2 n01 = *(const ulonglong2*)(row);
        ulonglong2 n23 = *(const ulonglong2*)(row + 4);
        ULL a0 = n01.x, a1 = n01.y, a2 = n23.x, a3 = n23.y;
        float2 wv = *(const float2*)&wta[k * 64 + lane * 2];
        ULL w0 = pk2(wv.x, wv.x), w1 = pk2(wv.y, wv.y);
        fma2(acc[0][0], w0, a0); fma2(acc[0][1], w0, a1); fma2(acc[0][2], w0, a2); fma2(acc[0][3], w0, a3);
        fma2(acc[1][0], w1, a0); fma2(acc[1][1], w1, a1); fma2(acc[1][2], w1, a2); fma2(acc[1][3], w1, a3);
    }

    __syncthreads();
#pragma unroll
    for (int i = 0; i < 2; i++) {
        int m = lane * 2 + i;
        float bv = ba[m];
#pragma unroll
        for (int p = 0; p < 4; p++) {
            float x, y; upk(acc[i][p], x, y);
            x += bv; y += bv;
            x = fmaxf(x, 0.01f * x); y = fmaxf(y, 0.01f * y);
            *(ULL*)&A_s[m * ASTRIDE + nb + 2 * p] = pk2(x, y);
        }
    }
    __syncthreads();

    ULL c2[2][4];
#pragma unroll
    for (int i = 0; i < 2; i++)
#pragma unroll
        for (int p = 0; p < 4; p++) c2[i][p] = 0ULL;
#pragma unroll 8
    for (int k = 0; k < 64; k++) {
        const float* row = &A_s[k * ASTRIDE + nb];
        ulonglong2 n01 = *(const ulonglong2*)(row);
        ulonglong2 n23 = *(const ulonglong2*)(row + 4);
        ULL a0 = n01.x, a1 = n01.y, a2 = n23.x, a3 = n23.y;
        float2 wv = *(const float2*)&wtb[k * 64 + lane * 2];
        ULL w0 = pk2(wv.x, wv.x), w1 = pk2(wv.y, wv.y);
        fma2(c2[0][0], w0, a0); fma2(c2[0][1], w0, a1); fma2(c2[0][2], w0, a2); fma2(c2[0][3], w0, a3);
        fma2(c2[1][0], w1, a0); fma2(c2[1][1], w1, a1); fma2(c2[1][2], w1, a2); fma2(c2[1][3], w1, a3);
    }
    float b0 = bb[lane * 2], b1 = bb[lane * 2 + 1];
    float s0 = 0.f, q0 = 0.f, s1 = 0.f, q1 = 0.f;
#pragma unroll
    for (int p = 0; p < 4; p++) {
        float x0, x1, y0, y1;
        upk(c2[0][p], x0, x1);
        upk(c2[1][p], y0, y1);
        int na = n0 + nb + 2 * p;
        if (na < N) {
            float o0 = x0 + b0, o1 = y0 + b1;
            sth2(&out[na * 64 + lane * 2], o0, o1);
            s0 += o0; q0 = fmaf(o0, o0, q0); s1 += o1; q1 = fmaf(o1, o1, q1);
        }
        if (na + 1 < N) {
            float o0 = x1 + b0, o1 = y1 + b1;
            sth2(&out[(na + 1) * 64 + lane * 2], o0, o1);
            s0 += o0; q0 = fmaf(o0, o0, q0); s1 += o1; q1 = fmaf(o1, o1, q1);
        }
    }
    RS[wrp * 64 + lane * 2] = s0; RS[wrp * 64 + lane * 2 + 1] = s1;
    RQ[wrp * 64 + lane * 2] = q0; RQ[wrp * 64 + lane * 2 + 1] = q1;
    __syncthreads();
    if (tid < 128) {
        int c = tid & 63;
        const float* P = (tid >= 64) ? RQ : RS;
        float v = 0.f;
#pragma unroll
        for (int w = 0; w < 8; w++) v += P[w * 64 + c];
        atomicAdd(&g_stats[bnidx * 128 + ((tid >= 64) ? 64 : 0) + c], v);
    }
}

// ---------------- fc1 head GEMM (fp16 pre in, fp32 out) -------------------
__global__ void __launch_bounds__(256) fc1_kernel(
    const __half* __restrict__ pre1, const __half* __restrict__ pre2, const __half* __restrict__ pre3,
    const float* __restrict__ bn0w, const float* __restrict__ bn0b,
    const float* __restrict__ bn1w, const float* __restrict__ bn1b,
    const float* __restrict__ bn2w, const float* __restrict__ bn2b,
    const float* __restrict__ fb,
    float* __restrict__ out, int N)
{
    extern __shared__ float smem[];
    float* A_s = smem;                      // 192*ASTRIDE
    float* RS  = A_s + 192 * ASTRIDE;       // 512
    float* RQ  = RS + 512;                  // 512
    float* sc  = RQ + 512;                  // 192
    float* sh  = sc + 192;                  // 192
    int*   s_comb = (int*)(sh + 192);       // 64

    const int tid = threadIdx.x;
    const int n0 = blockIdx.x * 64;
    if (tid < 192) {
        int l = tid >> 6, c = tid & 63;
        const float* w = (l == 0) ? bn0w : ((l == 1) ? bn1w : bn2w);
        const float* b = (l == 0) ? bn0b : ((l == 1) ? bn1b : bn2b);
        float m   = g_stats[l * 128 + c] / (float)N;
        float var = g_stats[l * 128 + 64 + c] / (float)N - m * m;
        float inv = rsqrtf(var + 1e-5f);
        float a   = w[c] * inv;
        sc[tid] = a;
        sh[tid] = b[c] - m * a;
    }
    if (tid >= 192 && tid < 256) {
        int nl = tid - 192;
        int n = n0 + nl;
        s_comb[nl] = (n < N) ? (g_comb[n] >> 1) : 0;   // U rows are 64 wide
    }
    __syncthreads();

    for (int i = tid; i < 64 * 192; i += 256) {
        int nl = i / 192, k = i - nl * 192;
        int n = n0 + nl;
        float v = 0.f;
        if (n < N) {
            int l = k >> 6, c = k & 63;
            const __half* pr = (l == 0) ? pre1 : ((l == 1) ? pre2 : pre3);
            float p = fmaf(__half2float(pr[n * 64 + c]), sc[k], sh[k]);
            v = fmaxf(p, 0.01f * p);
        }
        A_s[k * ASTRIDE + nl] = v;
    }
    __syncthreads();

    const int lane = tid & 31, wrp = tid >> 5;
    const int nb = wrp * 8;

    ULL c2[2][4];
#pragma unroll
    for (int i = 0; i < 2; i++)
#pragma unroll
        for (int p = 0; p < 4; p++) c2[i][p] = 0ULL;

#pragma unroll 8
    for (int k = 0; k < 192; k++) {
        const float* row = &A_s[k * ASTRIDE + nb];
        ulonglong2 n01 = *(const ulonglong2*)(row);
        ulonglong2 n23 = *(const ulonglong2*)(row + 4);
        ULL a0 = n01.x, a1 = n01.y, a2 = n23.x, a3 = n23.y;
        float2 wv = *(const float2*)&g_fc1t[(128 + k) * 64 + lane * 2];
        ULL w0 = pk2(wv.x, wv.x), w1 = pk2(wv.y, wv.y);
        fma2(c2[0][0], w0, a0); fma2(c2[0][1], w0, a1); fma2(c2[0][2], w0, a2); fma2(c2[0][3], w0, a3);
        fma2(c2[1][0], w1, a0); fma2(c2[1][1], w1, a1); fma2(c2[1][2], w1, a2); fma2(c2[1][3], w1, a3);
    }

    float b0 = fb[lane * 2], b1 = fb[lane * 2 + 1];
    float s0 = 0.f, q0 = 0.f, s1 = 0.f, q1 = 0.f;
#pragma unroll
    for (int p = 0; p < 4; p++) {
        float x0, x1, y0, y1;
        upk(c2[0][p], x0, x1);
        upk(c2[1][p], y0, y1);
        int na = n0 + nb + 2 * p;
        if (na < N) {
            float2 uv = *(const float2*)&g_U[s_comb[nb + 2 * p] + lane * 2];
            float o0 = x0 + b0 + uv.x, o1 = y0 + b1 + uv.y;
            *(float2*)&out[na * 64 + lane * 2] = make_float2(o0, o1);
            s0 += o0; q0 = fmaf(o0, o0, q0); s1 += o1; q1 = fmaf(o1, o1, q1);
        }
        if (na + 1 < N) {
            float2 uv = *(const float2*)&g_U[s_comb[nb + 2 * p + 1] + lane * 2];
            float o0 = x1 + b0 + uv.x, o1 = y1 + b1 + uv.y;
            *(float2*)&out[(na + 1) * 64 + lane * 2] = make_float2(o0, o1);
            s0 += o0; q0 = fmaf(o0, o0, q0); s1 += o1; q1 = fmaf(o1, o1, q1);
        }
    }
    RS[wrp * 64 + lane * 2] = s0; RS[wrp * 64 + lane * 2 + 1] = s1;
    RQ[wrp * 64 + lane * 2] = q0; RQ[wrp * 64 + lane * 2 + 1] = q1;
    __syncthreads();
    if (tid < 128) {
        int c = tid & 63;
        const float* P = (tid >= 64) ? RQ : RS;
        float v = 0.f;
#pragma unroll
        for (int w = 0; w < 8; w++) v += P[w * 64 + c];
        atomicAdd(&g_stats[3 * 128 + ((tid >= 64) ? 64 : 0) + c], v);
    }
}

// ---------------- final head ----------------
__global__ void final_kernel(const float* __restrict__ hpre,
                             const float* __restrict__ bnw, const float* __restrict__ bnb,
                             const float* __restrict__ fc2w, const float* __restrict__ fc2b,
                             float* __restrict__ out, int N) {
    __shared__ float sc[64], sh[64], w2s[64];
    if (threadIdx.x < 64) {
        int c = threadIdx.x;
        float m   = g_stats[3 * 128 + c] / (float)N;
        float var = g_stats[3 * 128 + 64 + c] / (float)N - m * m;
        float inv = rsqrtf(var + 1e-5f);
        float a   = bnw[c] * inv;
        sc[c]  = a;
        sh[c]  = bnb[c] - m * a;
        w2s[c] = fc2w[c];
    }
    __syncthreads();
    int wid  = (blockIdx.x * blockDim.x + threadIdx.x) >> 5;
    int lane = threadIdx.x & 31;
    if (wid >= N) return;
    float2 v = *(const float2*)&hpre[wid * 64 + lane * 2];
    float x = fmaf(v.x, sc[lane * 2], sh[lane * 2]);         x = fmaxf(x, 0.01f * x);
    float y = fmaf(v.y, sc[lane * 2 + 1], sh[lane * 2 + 1]); y = fmaxf(y, 0.01f * y);
    float acc = fmaf(x, w2s[lane * 2], y * w2s[lane * 2 + 1]);
#pragma unroll
    for (int off = 16; off; off >>= 1) acc += __shfl_xor_sync(0xffffffffu, acc, off);
    if (lane == 0) out[wid] = 1.f / (1.f + expf(-(acc + fc2b[0])));
}

// ---------------- launch ----------------
extern "C" void kernel_launch(void* const* d_in, const int* in_sizes, int n_in,
                              void* d_out, int out_size) {
    const float* emb_deg = (const float*)d_in[0];
    const float* emb_lab = (const float*)d_in[1];
    const float* w0a = (const float*)d_in[2];  const float* b0a = (const float*)d_in[3];
    const float* w0b = (const float*)d_in[4];  const float* b0b = (const float*)d_in[5];
    const float* bn0w = (const float*)d_in[6]; const float* bn0b = (const float*)d_in[7];
    const float* w1a = (const float*)d_in[8];  const float* b1a = (const float*)d_in[9];
    const float* w1b = (const float*)d_in[10]; const float* b1b = (const float*)d_in[11];
    const float* bn1w = (const float*)d_in[12]; const float* bn1b = (const float*)d_in[13];
    const float* w2a = (const float*)d_in[14]; const float* b2a = (const float*)d_in[15];
    const float* w2b = (const float*)d_in[16]; const float* b2b = (const float*)d_in[17];
    const float* bn2w = (const float*)d_in[18]; const float* bn2b = (const float*)d_in[19];
    const float* fc1w = (const float*)d_in[20]; const float* fc1b = (const float*)d_in[21];
    const float* fcbnw = (const float*)d_in[22]; const float* fcbnb = (const float*)d_in[23];
    const float* fc2w = (const float*)d_in[24]; const float* fc2b = (const float*)d_in[25];
    const int* node_deg = (const int*)d_in[26];
    const int* node_lab = (const int*)d_in[27];
    const int* edge = (const int*)d_in[28];

    const int N = in_sizes[26];
    const int E = in_sizes[28] / 2;
    const int* src  = edge;
    const int* dstp = edge + E;
    float* out = (float*)d_out;

    float *hin, *pre4;
    __half *pre1, *pre2, *pre3;
    float *wt0b, *wt1a, *wt1b, *wt2a, *wt2b;
    cudaGetSymbolAddress((void**)&hin,  g_hin);
    cudaGetSymbolAddress((void**)&pre1, g_pre1);
    cudaGetSymbolAddress((void**)&pre2, g_pre2);
    cudaGetSymbolAddress((void**)&pre3, g_pre3);
    cudaGetSymbolAddress((void**)&pre4, g_pre4);
    cudaGetSymbolAddress((void**)&wt0b, g_wt0b);
    cudaGetSymbolAddress((void**)&wt1a, g_wt1a);
    cudaGetSymbolAddress((void**)&wt1b, g_wt1b);
    cudaGetSymbolAddress((void**)&wt2a, g_wt2a);
    cudaGetSymbolAddress((void**)&wt2b, g_wt2b);

    const int TB = 256;
    const int mlpBlocks  = (N + 63) / 64;
    const int warpBlocks = (N * 32 + TB - 1) / TB;
    const int hwBlocks   = (N * 16 + TB - 1) / TB;
    const int scanBlocks = (N + 255) / 256;
    const int prepBlocks = (45056 + 255) / 256;

    const int SM_TBL   = (128 * ASTRIDE + 32 * 132) * 4;             // 51712
    const int SM_MLP0B = (128 * ASTRIDE + 1024) * 4;                 // 38912
    const int SM_MLP1  = (64 * ASTRIDE + 1024) * 4;                  // 21504
    const int SM_FC1   = (192 * ASTRIDE + 1024 + 384 + 64) * 4;      // 58112
    cudaFuncSetAttribute(tables_kernel, cudaFuncAttributeMaxDynamicSharedMemorySize, SM_TBL);
    cudaFuncSetAttribute(mlp0b_kernel,  cudaFuncAttributeMaxDynamicSharedMemorySize, SM_MLP0B);
    cudaFuncSetAttribute(mlp_kernel,    cudaFuncAttributeMaxDynamicSharedMemorySize, SM_MLP1);
    cudaFuncSetAttribute(fc1_kernel,    cudaFuncAttributeMaxDynamicSharedMemorySize, SM_FC1);

    static cudaStream_t sPrep = []() {
        cudaStream_t s; cudaStreamCreateWithFlags(&s, cudaStreamNonBlocking); return s;
    }();
    static cudaEvent_t evFork = []() {
        cudaEvent_t e; cudaEventCreateWithFlags(&e, cudaEventDisableTiming); return e;
    }();
    static cudaEvent_t evJoin = []() {
        cudaEvent_t e; cudaEventCreateWithFlags(&e, cudaEventDisableTiming); return e;
    }();

    // fork: prep branch on side stream
    cudaEventRecord(evFork, 0);
    cudaStreamWaitEvent(sPrep, evFork, 0);
    prep_kernel<<<prepBlocks, 256, 0, sPrep>>>(w0b, w1a, w1b, w2a, w2b, fc1w);
    tables_kernel<<<32, 256, SM_TBL, sPrep>>>(w0a, fc1w, emb_deg, emb_lab);
    cudaEventRecord(evJoin, sPrep);

    // CSR branch on main stream
    hist_kernel<<<(E + TB - 1) / TB, TB>>>(dstp, node_deg, node_lab, E, N);
    scan_kernel<<<scanBlocks, 256>>>(N);
    scatter_kernel<<<(E + TB - 1) / TB, TB>>>(src, dstp, E, N);

    // join
    cudaStreamWaitEvent(0, evJoin, 0);

    // layer 0
    agg0t_kernel<<<warpBlocks, TB>>>(hin, N);
    mlp0b_kernel<<<mlpBlocks, 256, SM_MLP0B>>>(hin, b0a, wt0b, b0b, pre1, N);

    // layer 1
    aggbn_kernel<<<hwBlocks, TB>>>(pre1, bn0w, bn0b, hin, N, 0);
    mlp_kernel<<<mlpBlocks, 256, SM_MLP1>>>(hin, wt1a, b1a, wt1b, b1b, pre2, N, 1);

    // layer 2
    aggbn_kernel<<<hwBlocks, TB>>>(pre2, bn1w, bn1b, hin, N, 1);
    mlp_kernel<<<mlpBlocks, 256, SM_MLP1>>>(hin, wt2a, b2a, wt2b, b2b, pre3, N, 2);

    // head
    fc1_kernel<<<mlpBlocks, 256, SM_FC1>>>(pre1, pre2, pre3,
                                           bn0w, bn0b, bn1w, bn1b, bn2w, bn2b,
                                           fc1b, pre4, N);
    final_kernel<<<warpBlocks, TB>>>(pre4, fcbnw, fcbnb, fc2w, fc2b, out, N);
}